// round 1
// baseline (speedup 1.0000x reference)
#include <cuda_runtime.h>
#include <math.h>

#define N_TOK    65536
#define C_DIM    256
#define E_NUM    64
#define S_SLOTS  131072
#define CAPACITY 2560
#define NCHUNK   128      /* S_SLOTS / 1024 */
#define NB2      8192     /* N_TOK / 8 router blocks */

// ---------------- scratch (device globals; no allocations) ----------------
__device__ float g_logits[N_TOK * E_NUM];          // 16.8 MB
__device__ int   g_eid[S_SLOTS];
__device__ float g_sc[S_SLOTS];
__device__ int   g_pos[S_SLOTS];
__device__ int   g_hist[NCHUNK * E_NUM];
__device__ int   g_chunkbase[NCHUNK * E_NUM];
__device__ int   g_kept[E_NUM];
__device__ int   g_tok[E_NUM * CAPACITY];
__device__ float g_ybuf[(size_t)E_NUM * CAPACITY * C_DIM];  // 167.8 MB
__device__ float g_gatesum[NB2 * E_NUM];           // 2 MB
__device__ float g_load[E_NUM];

// ---------------- packed fp32x2 helpers (Blackwell dual-FMA pipe) ----------
__device__ __forceinline__ unsigned long long splat2(float x) {
    unsigned long long r;
    asm("mov.b64 %0, {%1, %1};" : "=l"(r) : "f"(x));
    return r;
}
__device__ __forceinline__ void fma2(unsigned long long& d,
                                     unsigned long long a,
                                     unsigned long long b) {
    asm("fma.rn.f32x2 %0, %1, %2, %0;" : "+l"(d) : "l"(a), "l"(b));
}
__device__ __forceinline__ float lo2(unsigned long long v) {
    return __uint_as_float((unsigned)v);
}
__device__ __forceinline__ float hi2(unsigned long long v) {
    return __uint_as_float((unsigned)(v >> 32));
}

// ---------------- K1: logits = x @ W_gate  [65536,256]x[256,64] ------------
// BM=128 tokens, BN=64 experts, BK=16. 256 threads, 8 rows x 4 cols/thread.
__global__ __launch_bounds__(256, 2) void k_logits(const float* __restrict__ x,
                                                   const float* __restrict__ wg) {
    __shared__ float As[16][132];
    __shared__ float Bs[16][68];
    int tid = threadIdx.x;
    int tx = tid & 15, ty = tid >> 4;
    int row0 = blockIdx.x * 128;

    unsigned long long acc[8][2];
#pragma unroll
    for (int i = 0; i < 8; i++) { acc[i][0] = 0ULL; acc[i][1] = 0ULL; }

    const float4* x4 = (const float4*)x;
    const float4* w4 = (const float4*)wg;

    for (int kb = 0; kb < 16; kb++) {
        // As[k][m] (transposed): 128 rows x 16 k
        for (int l = tid; l < 512; l += 256) {
            int m = l >> 2, cs = l & 3;
            float4 v = x4[(size_t)(row0 + m) * 64 + kb * 4 + cs];
            As[cs * 4 + 0][m] = v.x; As[cs * 4 + 1][m] = v.y;
            As[cs * 4 + 2][m] = v.z; As[cs * 4 + 3][m] = v.w;
        }
        // Bs[k][n]: 16 x 64
        {
            int kk = tid >> 4, n4 = tid & 15;
            float4 v = w4[(size_t)(kb * 16 + kk) * 16 + n4];
            *(float4*)&Bs[kk][n4 * 4] = v;
        }
        __syncthreads();
#pragma unroll
        for (int kk = 0; kk < 16; kk++) {
            ulonglong2 bb = *(const ulonglong2*)&Bs[kk][tx * 4];
            float a[8];
            *(float4*)&a[0] = *(const float4*)&As[kk][ty * 8];
            *(float4*)&a[4] = *(const float4*)&As[kk][ty * 8 + 4];
#pragma unroll
            for (int i = 0; i < 8; i++) {
                unsigned long long s = splat2(a[i]);
                fma2(acc[i][0], s, bb.x);
                fma2(acc[i][1], s, bb.y);
            }
        }
        __syncthreads();
    }
#pragma unroll
    for (int i = 0; i < 8; i++) {
        int r = row0 + ty * 8 + i;
        float4 o;
        o.x = lo2(acc[i][0]); o.y = hi2(acc[i][0]);
        o.z = lo2(acc[i][1]); o.w = hi2(acc[i][1]);
        ((float4*)g_logits)[(size_t)r * 16 + tx] = o;
    }
}

// ---------------- K2: softmax + top-2 per token (1 warp/token) -------------
__global__ __launch_bounds__(256) void k_router() {
    __shared__ float sg[8][64];
    int tid = threadIdx.x, lane = tid & 31, w = tid >> 5;
    int tok = blockIdx.x * 8 + w;
    const float* lg = g_logits + (size_t)tok * 64;
    float v0 = lg[lane], v1 = lg[lane + 32];

    float mx = fmaxf(v0, v1);
#pragma unroll
    for (int o = 16; o; o >>= 1) mx = fmaxf(mx, __shfl_xor_sync(0xffffffffu, mx, o));
    float e0 = expf(v0 - mx), e1 = expf(v1 - mx);
    float sum = e0 + e1;
#pragma unroll
    for (int o = 16; o; o >>= 1) sum += __shfl_xor_sync(0xffffffffu, sum, o);
    float g0 = e0 / sum, g1 = e1 / sum;

    // top-1 on logits (monotonic with gates); tie -> lower index
    float bv; int bi;
    if (v1 > v0) { bv = v1; bi = lane + 32; } else { bv = v0; bi = lane; }
#pragma unroll
    for (int o = 16; o; o >>= 1) {
        float ov = __shfl_xor_sync(0xffffffffu, bv, o);
        int   oi = __shfl_xor_sync(0xffffffffu, bi, o);
        if (ov > bv || (ov == bv && oi < bi)) { bv = ov; bi = oi; }
    }
    int i1 = bi;

    const float NEG = __int_as_float(0xff800000);
    float w0 = (lane == i1) ? NEG : v0;
    float w1 = (lane + 32 == i1) ? NEG : v1;
    float cv; int ci;
    if (w1 > w0) { cv = w1; ci = lane + 32; } else { cv = w0; ci = lane; }
#pragma unroll
    for (int o = 16; o; o >>= 1) {
        float ov = __shfl_xor_sync(0xffffffffu, cv, o);
        int   oi = __shfl_xor_sync(0xffffffffu, ci, o);
        if (ov > cv || (ov == cv && oi < ci)) { cv = ov; ci = oi; }
    }
    int i2 = ci;

    float s1 = __shfl_sync(0xffffffffu, (i1 < 32) ? g0 : g1, i1 & 31);
    float s2 = __shfl_sync(0xffffffffu, (i2 < 32) ? g0 : g1, i2 & 31);

    if (lane == 0) {
        g_eid[2 * tok] = i1;     g_sc[2 * tok] = s1;
        g_eid[2 * tok + 1] = i2; g_sc[2 * tok + 1] = s2;
    }

    sg[w][lane] = g0; sg[w][lane + 32] = g1;
    __syncthreads();
    if (tid < 64) {
        float s = 0.0f;
#pragma unroll
        for (int j = 0; j < 8; j++) s += sg[j][tid];
        g_gatesum[(size_t)blockIdx.x * 64 + tid] = s;
    }
}

// ---------------- K3: per-chunk expert histograms (chunks of 1024 slots) ---
__global__ __launch_bounds__(256) void k_hist() {
    __shared__ int h[64];
    int tid = threadIdx.x;
    if (tid < 64) h[tid] = 0;
    __syncthreads();
    int base = blockIdx.x * 1024;
#pragma unroll
    for (int j = 0; j < 4; j++) atomicAdd(&h[g_eid[base + j * 256 + tid]], 1);
    __syncthreads();
    if (tid < 64) g_hist[blockIdx.x * 64 + tid] = h[tid];
}

// ---------------- K4: exclusive scan over chunks per expert ----------------
__global__ void k_scan() {
    int e = threadIdx.x;  // 64 threads
    int run = 0;
    for (int c = 0; c < NCHUNK; c++) {
        g_chunkbase[c * 64 + e] = run;
        run += g_hist[c * 64 + e];
    }
    g_kept[e] = (run < CAPACITY) ? run : CAPACITY;
}

// ---------------- K5: exact FIFO ranks + expert token lists ----------------
__global__ __launch_bounds__(1024) void k_rank() {
    __shared__ int se[1024];
    int t = threadIdx.x;
    int slot = blockIdx.x * 1024 + t;
    int e = g_eid[slot];
    se[t] = e;
    __syncthreads();
    int cnt = 0;
    for (int j = 0; j < t; j++) cnt += (se[j] == e);
    int rank = g_chunkbase[blockIdx.x * 64 + e] + cnt;
    if (rank < CAPACITY) {
        int p = e * CAPACITY + rank;
        g_pos[slot] = p;
        g_tok[p] = slot >> 1;
    } else {
        g_pos[slot] = -1;
    }
}

// ---------------- K6: grouped expert GEMM (gathered rows) ------------------
// Per expert: Y[m,n] = X[tok[m],k] * W_e[k,n]. BM=128, BN=128, BK=16.
// 256 threads, 8x8 micro-tile as 4 row-pairs x 8 cols, packed f32x2 FMA.
__global__ __launch_bounds__(256, 2) void k_gemm(const float* __restrict__ x,
                                                 const float* __restrict__ we) {
    __shared__ float As[16][132];
    __shared__ float Bs[16][132];
    __shared__ int stok[128];

    int e = blockIdx.z;
    int kept = g_kept[e];
    int m0 = blockIdx.x * 128;
    if (m0 >= kept) return;
    int n0 = blockIdx.y * 128;
    int tid = threadIdx.x, tx = tid & 15, ty = tid >> 4;

    if (tid < 128) {
        int r = m0 + tid;
        stok[tid] = (r < kept) ? g_tok[e * CAPACITY + r] : -1;
    }
    __syncthreads();

    unsigned long long acc[4][8];
#pragma unroll
    for (int p = 0; p < 4; p++)
#pragma unroll
        for (int j = 0; j < 8; j++) acc[p][j] = 0ULL;

    const float4* x4 = (const float4*)x;
    const float4* w4 = (const float4*)we + (size_t)e * 16384;  // e*256*256/4

    for (int kb = 0; kb < 16; kb++) {
        // As[k][m]: gathered 128 rows x 16 k
        for (int l = tid; l < 512; l += 256) {
            int m = l >> 2, cs = l & 3;
            int tk = stok[m];
            float4 v = make_float4(0.f, 0.f, 0.f, 0.f);
            if (tk >= 0) v = x4[(size_t)tk * 64 + kb * 4 + cs];
            As[cs * 4 + 0][m] = v.x; As[cs * 4 + 1][m] = v.y;
            As[cs * 4 + 2][m] = v.z; As[cs * 4 + 3][m] = v.w;
        }
        // Bs[k][n]: 16 x 128 from W_e
        for (int l = tid; l < 512; l += 256) {
            int kk = l >> 5, n4 = l & 31;
            float4 v = w4[(size_t)(kb * 16 + kk) * 64 + (n0 >> 2) + n4];
            *(float4*)&Bs[kk][n4 * 4] = v;
        }
        __syncthreads();
#pragma unroll
        for (int kk = 0; kk < 16; kk++) {
            ulonglong2 A0 = *(const ulonglong2*)&As[kk][ty * 8];
            ulonglong2 A1 = *(const ulonglong2*)&As[kk][ty * 8 + 4];
            unsigned long long ar[4] = {A0.x, A0.y, A1.x, A1.y};
            float bcol[8];
            *(float4*)&bcol[0] = *(const float4*)&Bs[kk][tx * 8];
            *(float4*)&bcol[4] = *(const float4*)&Bs[kk][tx * 8 + 4];
#pragma unroll
            for (int j = 0; j < 8; j++) {
                unsigned long long bs = splat2(bcol[j]);
#pragma unroll
                for (int p = 0; p < 4; p++) fma2(acc[p][j], ar[p], bs);
            }
        }
        __syncthreads();
    }

    // epilogue: unscaled y into the expert buffer
#pragma unroll
    for (int p = 0; p < 4; p++) {
        int rl = m0 + ty * 8 + 2 * p;
        if (rl < kept) {
            float4 a, b;
            a.x = lo2(acc[p][0]); a.y = lo2(acc[p][1]); a.z = lo2(acc[p][2]); a.w = lo2(acc[p][3]);
            b.x = lo2(acc[p][4]); b.y = lo2(acc[p][5]); b.z = lo2(acc[p][6]); b.w = lo2(acc[p][7]);
            float* d = g_ybuf + ((size_t)e * CAPACITY + rl) * 256 + n0 + tx * 8;
            *(float4*)d = a; *(float4*)(d + 4) = b;
        }
        int rh = rl + 1;
        if (rh < kept) {
            float4 a, b;
            a.x = hi2(acc[p][0]); a.y = hi2(acc[p][1]); a.z = hi2(acc[p][2]); a.w = hi2(acc[p][3]);
            b.x = hi2(acc[p][4]); b.y = hi2(acc[p][5]); b.z = hi2(acc[p][6]); b.w = hi2(acc[p][7]);
            float* d = g_ybuf + ((size_t)e * CAPACITY + rh) * 256 + n0 + tx * 8;
            *(float4*)d = a; *(float4*)(d + 4) = b;
        }
    }
}

// ---------------- K_combine: out[tok] = s0*y[p0] + s1*y[p1] ----------------
__global__ __launch_bounds__(256) void k_combine(float* __restrict__ out) {
    int idx = blockIdx.x * 256 + threadIdx.x;  // over N_TOK*64 float4s
    int tok = idx >> 6, c4 = idx & 63;
    int p0 = g_pos[2 * tok], p1 = g_pos[2 * tok + 1];
    float s0 = g_sc[2 * tok], s1 = g_sc[2 * tok + 1];
    float4 r = make_float4(0.f, 0.f, 0.f, 0.f);
    const float4* yb = (const float4*)g_ybuf;
    if (p0 >= 0) {
        float4 y = yb[(size_t)p0 * 64 + c4];
        r.x = s0 * y.x; r.y = s0 * y.y; r.z = s0 * y.z; r.w = s0 * y.w;
    }
    if (p1 >= 0) {
        float4 y = yb[(size_t)p1 * 64 + c4];
        r.x += s1 * y.x; r.y += s1 * y.y; r.z += s1 * y.z; r.w += s1 * y.w;
    }
    ((float4*)out)[idx] = r;
}

// ---------------- K7a/K7b: deterministic aux-loss reduction ----------------
__global__ __launch_bounds__(256) void k_loadsum() {
    __shared__ float sh[256];
    int e = blockIdx.x;
    float s = 0.0f;
    for (int b = threadIdx.x; b < NB2; b += 256) s += g_gatesum[(size_t)b * 64 + e];
    sh[threadIdx.x] = s;
    __syncthreads();
    for (int o = 128; o; o >>= 1) {
        if (threadIdx.x < o) sh[threadIdx.x] += sh[threadIdx.x + o];
        __syncthreads();
    }
    if (threadIdx.x == 0) g_load[e] = sh[0];
}

__global__ void k_aux(float* __restrict__ out, int out_size) {
    __shared__ float sh[64];
    int e = threadIdx.x;
    float load = g_load[e] / (float)N_TOK;
    float d = load - (1.0f / 64.0f);
    sh[e] = d * d;
    __syncthreads();
    for (int o = 32; o; o >>= 1) {
        if (e < o) sh[e] += sh[e + o];
        __syncthreads();
    }
    if (e == 0 && out_size > N_TOK * C_DIM) out[N_TOK * C_DIM] = sh[0] / 64.0f;
}

// ---------------- launch ---------------------------------------------------
extern "C" void kernel_launch(void* const* d_in, const int* in_sizes, int n_in,
                              void* d_out, int out_size) {
    const float* x  = (const float*)d_in[0];   // [8,8192,256]
    const float* wg = (const float*)d_in[1];   // [256,64]
    const float* we = (const float*)d_in[2];   // [64,256,256]
    float* out = (float*)d_out;

    k_logits <<<512, 256>>>(x, wg);
    k_router <<<NB2, 256>>>();
    k_hist   <<<NCHUNK, 256>>>();
    k_scan   <<<1, 64>>>();
    k_rank   <<<NCHUNK, 1024>>>();
    k_gemm   <<<dim3(CAPACITY / 128, 2, E_NUM), 256>>>(x, we);
    k_combine<<<N_TOK / 4, 256>>>(out);
    k_loadsum<<<E_NUM, 256>>>();
    k_aux    <<<1, 64>>>(out, out_size);
}

// round 3
// speedup vs baseline: 1.3926x; 1.3926x over previous
#include <cuda_runtime.h>
#include <cuda_bf16.h>
#include <math.h>
#include <stdint.h>

#define N_TOK    65536
#define C_DIM    256
#define E_NUM    64
#define S_SLOTS  131072
#define CAPACITY 2560
#define NCHUNK   128      /* S_SLOTS / 1024 */
#define NB2      8192     /* N_TOK / 8 router blocks */

// ---------------- scratch (device globals; no allocations) ----------------
__device__ float g_logits[N_TOK * E_NUM];
__device__ int   g_eid[S_SLOTS];
__device__ float g_sc[S_SLOTS];
__device__ int   g_pos[S_SLOTS];
__device__ int   g_hist[NCHUNK * E_NUM];
__device__ int   g_chunkbase[NCHUNK * E_NUM];
__device__ int   g_kept[E_NUM];
__device__ int   g_tok[E_NUM * CAPACITY];
__device__ float g_ybuf[(size_t)E_NUM * CAPACITY * C_DIM];
__device__ float g_gatesum[NB2 * E_NUM];
__device__ float g_load[E_NUM];
// bf16 hi/lo splits
__device__ __nv_bfloat16 g_xhi[(size_t)N_TOK * C_DIM];
__device__ __nv_bfloat16 g_xlo[(size_t)N_TOK * C_DIM];
__device__ __nv_bfloat16 g_wthi[(size_t)E_NUM * C_DIM * C_DIM];  // [e][n][k]
__device__ __nv_bfloat16 g_wtlo[(size_t)E_NUM * C_DIM * C_DIM];

// ---------------- packed fp32x2 helpers -------------------------------------
__device__ __forceinline__ unsigned long long splat2(float x) {
    unsigned long long r;
    asm("mov.b64 %0, {%1, %1};" : "=l"(r) : "f"(x));
    return r;
}
__device__ __forceinline__ void fma2(unsigned long long& d, unsigned long long a,
                                     unsigned long long b) {
    asm("fma.rn.f32x2 %0, %1, %2, %0;" : "+l"(d) : "l"(a), "l"(b));
}
__device__ __forceinline__ float lo2(unsigned long long v) { return __uint_as_float((unsigned)v); }
__device__ __forceinline__ float hi2(unsigned long long v) { return __uint_as_float((unsigned)(v >> 32)); }

// ---------------- mma.sync helpers (base sm_103-safe) ------------------------
__device__ __forceinline__ uint32_t smem_u32(const void* p) {
    uint32_t a;
    asm("{ .reg .u64 t; cvta.to.shared.u64 t, %1; cvt.u32.u64 %0, t; }"
        : "=r"(a) : "l"(p));
    return a;
}
__device__ __forceinline__ void ldsm_x4(uint32_t* r, uint32_t a) {
    asm volatile("ldmatrix.sync.aligned.m8n8.x4.shared.b16 {%0,%1,%2,%3}, [%4];"
                 : "=r"(r[0]), "=r"(r[1]), "=r"(r[2]), "=r"(r[3]) : "r"(a));
}
__device__ __forceinline__ void ldsm_x2(uint32_t* r, uint32_t a) {
    asm volatile("ldmatrix.sync.aligned.m8n8.x2.shared.b16 {%0,%1}, [%2];"
                 : "=r"(r[0]), "=r"(r[1]) : "r"(a));
}
__device__ __forceinline__ void mma_bf16(float* d, const uint32_t* a, const uint32_t* b) {
    asm volatile(
        "mma.sync.aligned.m16n8k16.row.col.f32.bf16.bf16.f32 "
        "{%0,%1,%2,%3}, {%4,%5,%6,%7}, {%8,%9}, {%0,%1,%2,%3};"
        : "+f"(d[0]), "+f"(d[1]), "+f"(d[2]), "+f"(d[3])
        : "r"(a[0]), "r"(a[1]), "r"(a[2]), "r"(a[3]), "r"(b[0]), "r"(b[1]));
}

// ---------------- K1: logits = x @ W_gate -----------------------------------
__global__ __launch_bounds__(256, 2) void k_logits(const float* __restrict__ x,
                                                   const float* __restrict__ wg) {
    __shared__ float As[16][132];
    __shared__ float Bs[16][68];
    int tid = threadIdx.x;
    int tx = tid & 15, ty = tid >> 4;
    int row0 = blockIdx.x * 128;

    unsigned long long acc[8][2];
#pragma unroll
    for (int i = 0; i < 8; i++) { acc[i][0] = 0ULL; acc[i][1] = 0ULL; }

    const float4* x4 = (const float4*)x;
    const float4* w4 = (const float4*)wg;

    for (int kb = 0; kb < 16; kb++) {
        for (int l = tid; l < 512; l += 256) {
            int m = l >> 2, cs = l & 3;
            float4 v = x4[(size_t)(row0 + m) * 64 + kb * 4 + cs];
            As[cs * 4 + 0][m] = v.x; As[cs * 4 + 1][m] = v.y;
            As[cs * 4 + 2][m] = v.z; As[cs * 4 + 3][m] = v.w;
        }
        {
            int kk = tid >> 4, n4 = tid & 15;
            float4 v = w4[(size_t)(kb * 16 + kk) * 16 + n4];
            *(float4*)&Bs[kk][n4 * 4] = v;
        }
        __syncthreads();
#pragma unroll
        for (int kk = 0; kk < 16; kk++) {
            ulonglong2 bb = *(const ulonglong2*)&Bs[kk][tx * 4];
            float a[8];
            *(float4*)&a[0] = *(const float4*)&As[kk][ty * 8];
            *(float4*)&a[4] = *(const float4*)&As[kk][ty * 8 + 4];
#pragma unroll
            for (int i = 0; i < 8; i++) {
                unsigned long long s = splat2(a[i]);
                fma2(acc[i][0], s, bb.x);
                fma2(acc[i][1], s, bb.y);
            }
        }
        __syncthreads();
    }
#pragma unroll
    for (int i = 0; i < 8; i++) {
        int r = row0 + ty * 8 + i;
        float4 o;
        o.x = lo2(acc[i][0]); o.y = hi2(acc[i][0]);
        o.z = lo2(acc[i][1]); o.w = hi2(acc[i][1]);
        ((float4*)g_logits)[(size_t)r * 16 + tx] = o;
    }
}

// ---------------- K2: softmax + top-2 ---------------------------------------
__global__ __launch_bounds__(256) void k_router() {
    __shared__ float sg[8][64];
    int tid = threadIdx.x, lane = tid & 31, w = tid >> 5;
    int tok = blockIdx.x * 8 + w;
    const float* lg = g_logits + (size_t)tok * 64;
    float v0 = lg[lane], v1 = lg[lane + 32];

    float mx = fmaxf(v0, v1);
#pragma unroll
    for (int o = 16; o; o >>= 1) mx = fmaxf(mx, __shfl_xor_sync(0xffffffffu, mx, o));
    float e0 = expf(v0 - mx), e1 = expf(v1 - mx);
    float sum = e0 + e1;
#pragma unroll
    for (int o = 16; o; o >>= 1) sum += __shfl_xor_sync(0xffffffffu, sum, o);
    float g0 = e0 / sum, g1 = e1 / sum;

    float bv; int bi;
    if (v1 > v0) { bv = v1; bi = lane + 32; } else { bv = v0; bi = lane; }
#pragma unroll
    for (int o = 16; o; o >>= 1) {
        float ov = __shfl_xor_sync(0xffffffffu, bv, o);
        int   oi = __shfl_xor_sync(0xffffffffu, bi, o);
        if (ov > bv || (ov == bv && oi < bi)) { bv = ov; bi = oi; }
    }
    int i1 = bi;

    const float NEG = __int_as_float(0xff800000);
    float w0 = (lane == i1) ? NEG : v0;
    float w1 = (lane + 32 == i1) ? NEG : v1;
    float cv; int ci;
    if (w1 > w0) { cv = w1; ci = lane + 32; } else { cv = w0; ci = lane; }
#pragma unroll
    for (int o = 16; o; o >>= 1) {
        float ov = __shfl_xor_sync(0xffffffffu, cv, o);
        int   oi = __shfl_xor_sync(0xffffffffu, ci, o);
        if (ov > cv || (ov == cv && oi < ci)) { cv = ov; ci = oi; }
    }
    int i2 = ci;

    float s1 = __shfl_sync(0xffffffffu, (i1 < 32) ? g0 : g1, i1 & 31);
    float s2 = __shfl_sync(0xffffffffu, (i2 < 32) ? g0 : g1, i2 & 31);

    if (lane == 0) {
        g_eid[2 * tok] = i1;     g_sc[2 * tok] = s1;
        g_eid[2 * tok + 1] = i2; g_sc[2 * tok + 1] = s2;
    }
    sg[w][lane] = g0; sg[w][lane + 32] = g1;
    __syncthreads();
    if (tid < 64) {
        float s = 0.0f;
#pragma unroll
        for (int j = 0; j < 8; j++) s += sg[j][tid];
        g_gatesum[(size_t)blockIdx.x * 64 + tid] = s;
    }
}

// ---------------- K3: per-chunk expert histograms ---------------------------
__global__ __launch_bounds__(256) void k_hist() {
    __shared__ int h[64];
    int tid = threadIdx.x;
    if (tid < 64) h[tid] = 0;
    __syncthreads();
    int base = blockIdx.x * 1024;
#pragma unroll
    for (int j = 0; j < 4; j++) atomicAdd(&h[g_eid[base + j * 256 + tid]], 1);
    __syncthreads();
    if (tid < 64) g_hist[blockIdx.x * 64 + tid] = h[tid];
}

// ---------------- K4: parallel exclusive scan per expert --------------------
__global__ __launch_bounds__(128) void k_scan() {
    __shared__ int s[128];
    int e = blockIdx.x, t = threadIdx.x;
    int v = g_hist[t * 64 + e];
    s[t] = v;
    __syncthreads();
#pragma unroll
    for (int o = 1; o < 128; o <<= 1) {
        int x = (t >= o) ? s[t - o] : 0;
        __syncthreads();
        s[t] += x;
        __syncthreads();
    }
    g_chunkbase[t * 64 + e] = s[t] - v;
    if (t == 127) g_kept[e] = (s[127] < CAPACITY) ? s[127] : CAPACITY;
}

// ---------------- K5: FIFO ranks via warp ballots ---------------------------
__global__ __launch_bounds__(1024) void k_rank() {
    __shared__ int whist[32][64];
    int t = threadIdx.x, lane = t & 31, w = t >> 5;
    int slot = blockIdx.x * 1024 + t;
    int e = g_eid[slot];
    ((int*)whist)[t] = 0;
    ((int*)whist)[t + 1024] = 0;
    __syncthreads();
    unsigned peers = __match_any_sync(0xffffffffu, e);
    int lr = __popc(peers & ((1u << lane) - 1u));
    if (lr == 0) whist[w][e] = __popc(peers);
    __syncthreads();
    int base = g_chunkbase[blockIdx.x * 64 + e];
    for (int j = 0; j < w; j++) base += whist[j][e];
    int rank = base + lr;
    if (rank < CAPACITY) {
        int p = e * CAPACITY + rank;
        g_pos[slot] = p;
        g_tok[p] = slot >> 1;
    } else {
        g_pos[slot] = -1;
    }
}

// ---------------- K_cvx: x -> bf16 hi/lo ------------------------------------
__global__ __launch_bounds__(256) void k_convert_x(const float* __restrict__ x) {
    size_t i = (size_t)blockIdx.x * 256 + threadIdx.x;
    float4 v = ((const float4*)x)[i];
    float f[4] = {v.x, v.y, v.z, v.w};
    unsigned short h[4], l[4];
#pragma unroll
    for (int j = 0; j < 4; j++) {
        __nv_bfloat16 hb = __float2bfloat16_rn(f[j]);
        __nv_bfloat16 lb = __float2bfloat16_rn(f[j] - __bfloat162float(hb));
        h[j] = __bfloat16_as_ushort(hb);
        l[j] = __bfloat16_as_ushort(lb);
    }
    uint2 ph, pl;
    ph.x = (unsigned)h[0] | ((unsigned)h[1] << 16);
    ph.y = (unsigned)h[2] | ((unsigned)h[3] << 16);
    pl.x = (unsigned)l[0] | ((unsigned)l[1] << 16);
    pl.y = (unsigned)l[2] | ((unsigned)l[3] << 16);
    ((uint2*)g_xhi)[i] = ph;
    ((uint2*)g_xlo)[i] = pl;
}

// ---------------- K_cvw: W_e[k][n] -> Wt[e][n][k] bf16 hi/lo ----------------
__global__ void k_convert_wt(const float* __restrict__ we) {
    __shared__ float ts[32][33];
    int e = blockIdx.z, kt = blockIdx.y, nt = blockIdx.x;
    int tx = threadIdx.x, ty = threadIdx.y;  // (32,8)
    const float* src = we + ((size_t)e * 256 + (size_t)kt * 32) * 256 + nt * 32;
#pragma unroll
    for (int j = 0; j < 32; j += 8) ts[ty + j][tx] = src[(size_t)(ty + j) * 256 + tx];
    __syncthreads();
#pragma unroll
    for (int j = 0; j < 32; j += 8) {
        float vv = ts[tx][ty + j];
        __nv_bfloat16 hb = __float2bfloat16_rn(vv);
        __nv_bfloat16 lb = __float2bfloat16_rn(vv - __bfloat162float(hb));
        size_t d = ((size_t)e * 256 + (size_t)nt * 32 + ty + j) * 256 + kt * 32 + tx;
        g_wthi[d] = hb;
        g_wtlo[d] = lb;
    }
}

// ---------------- K6: grouped GEMM on HMMA (bf16 hi/lo split) ----------------
// CTA: 128 gathered rows x 128 cols, K=256 in 4 chunks of 64.
// 8 warps, warp tile 64x32 (4 m-tiles x 4 n-tiles of m16n8k16).
// SMEM tiles with 72-bf16 (144B) row pitch; ldmatrix fragment loads.
#define KCH      64
#define PITCH    72                       /* bf16 per row */
#define TB       (128 * PITCH * 2)        /* 18432 B per tile */
#define OFF_AH   0
#define OFF_AL   (TB)
#define OFF_BH   (2 * TB)
#define OFF_BL   (3 * TB)
#define OFF_TOK  (4 * TB)
#define GM_SMEM  (4 * TB + 512)

__global__ __launch_bounds__(256, 1) void k_gemm_hmma() {
    extern __shared__ char sm[];
    const uint32_t smb = smem_u32(sm);
    int tid = threadIdx.x, lane = tid & 31, wid = tid >> 5;

    int e = blockIdx.z;
    int kept = g_kept[e];
    int m0 = blockIdx.x * 128;
    if (m0 >= kept) return;
    int n0 = blockIdx.y * 128;

    int* stok = (int*)(sm + OFF_TOK);
    if (tid < 128) {
        int r = m0 + tid;
        stok[tid] = (r < kept) ? g_tok[e * CAPACITY + r] : -1;
    }
    __syncthreads();

    int wm = wid >> 2, wn = wid & 3;     // warp tile: rows wm*64, cols wn*32

    float acc[4][4][4];
#pragma unroll
    for (int mt = 0; mt < 4; mt++)
#pragma unroll
        for (int nt = 0; nt < 4; nt++)
#pragma unroll
            for (int q = 0; q < 4; q++) acc[mt][nt][q] = 0.0f;

    const uint4* xh4 = (const uint4*)g_xhi;
    const uint4* xl4 = (const uint4*)g_xlo;
    const uint4* wh4 = (const uint4*)g_wthi;
    const uint4* wl4 = (const uint4*)g_wtlo;
    const uint4 z4 = make_uint4(0, 0, 0, 0);

    // precomputed ldmatrix lane addresses (depend on k0 added later)
    int a_m = lane >> 3, a_r = lane & 7;
    int b_l = lane & 15;

    for (int kc = 0; kc < 4; kc++) {
        // ---- load chunk: A (gathered) and B, hi+lo, 16B vectors ----
#pragma unroll
        for (int j = 0; j < 4; j++) {
            int idx = j * 256 + tid;           // 0..1023
            int row = idx >> 3, c8 = idx & 7;
            int tk = stok[row];
            uint4 vh = z4, vl = z4;
            if (tk >= 0) {
                size_t s = (size_t)tk * 32 + kc * 8 + c8;
                vh = xh4[s]; vl = xl4[s];
            }
            uint32_t o = (uint32_t)(row * 144 + c8 * 16);
            *(uint4*)(sm + OFF_AH + o) = vh;
            *(uint4*)(sm + OFF_AL + o) = vl;
        }
#pragma unroll
        for (int j = 0; j < 4; j++) {
            int idx = j * 256 + tid;
            int row = idx >> 3, c8 = idx & 7;
            size_t s = (size_t)(e * 256 + n0 + row) * 32 + kc * 8 + c8;
            uint32_t o = (uint32_t)(row * 144 + c8 * 16);
            *(uint4*)(sm + OFF_BH + o) = wh4[s];
            *(uint4*)(sm + OFF_BL + o) = wl4[s];
        }
        __syncthreads();

        // ---- 4 k16 steps ----
#pragma unroll
        for (int ks = 0; ks < 4; ks++) {
            int k0 = ks * 16;
            uint32_t ah[4][4], al[4][4], bh[4][2], bl[4][2];
#pragma unroll
            for (int mt = 0; mt < 4; mt++) {
                int arow = wm * 64 + mt * 16 + (a_m & 1) * 8 + a_r;
                int acol = k0 + (a_m >> 1) * 8;
                uint32_t off = (uint32_t)(arow * 144 + acol * 2);
                ldsm_x4(ah[mt], smb + OFF_AH + off);
                ldsm_x4(al[mt], smb + OFF_AL + off);
            }
#pragma unroll
            for (int nt = 0; nt < 4; nt++) {
                int brow = wn * 32 + nt * 8 + (b_l & 7);
                int bcol = k0 + ((b_l >> 3) & 1) * 8;
                uint32_t off = (uint32_t)(brow * 144 + bcol * 2);
                ldsm_x2(bh[nt], smb + OFF_BH + off);
                ldsm_x2(bl[nt], smb + OFF_BL + off);
            }
#pragma unroll
            for (int mt = 0; mt < 4; mt++)
#pragma unroll
                for (int nt = 0; nt < 4; nt++) {
                    mma_bf16(acc[mt][nt], ah[mt], bh[nt]);
                    mma_bf16(acc[mt][nt], ah[mt], bl[nt]);
                    mma_bf16(acc[mt][nt], al[mt], bh[nt]);
                }
        }
        __syncthreads();
    }

    // ---- epilogue: stage through SMEM for coalesced stores ----
    float* fb = (float*)sm;                      // [128][132]
    int g = lane >> 2, c = lane & 3;
#pragma unroll
    for (int mt = 0; mt < 4; mt++) {
#pragma unroll
        for (int nt = 0; nt < 4; nt++) {
            int row = wm * 64 + mt * 16 + g;
            int col = wn * 32 + nt * 8 + c * 2;
            float2 v0 = make_float2(acc[mt][nt][0], acc[mt][nt][1]);
            float2 v1 = make_float2(acc[mt][nt][2], acc[mt][nt][3]);
            *(float2*)&fb[row * 132 + col] = v0;
            *(float2*)&fb[(row + 8) * 132 + col] = v1;
        }
    }
    __syncthreads();
    int c4 = tid & 31;
#pragma unroll
    for (int rp = 0; rp < 16; rp++) {
        int row = rp * 8 + (tid >> 5);
        if (m0 + row < kept) {
            float4 v = *(const float4*)&fb[row * 132 + c4 * 4];
            *(float4*)(g_ybuf + ((size_t)e * CAPACITY + m0 + row) * 256 + n0 + c4 * 4) = v;
        }
    }
}

// ---------------- K_combine --------------------------------------------------
__global__ __launch_bounds__(256) void k_combine(float* __restrict__ out) {
    int idx = blockIdx.x * 256 + threadIdx.x;
    int tok = idx >> 6, c4 = idx & 63;
    int p0 = g_pos[2 * tok], p1 = g_pos[2 * tok + 1];
    float s0 = g_sc[2 * tok], s1 = g_sc[2 * tok + 1];
    float4 r = make_float4(0.f, 0.f, 0.f, 0.f);
    const float4* yb = (const float4*)g_ybuf;
    if (p0 >= 0) {
        float4 y = yb[(size_t)p0 * 64 + c4];
        r.x = s0 * y.x; r.y = s0 * y.y; r.z = s0 * y.z; r.w = s0 * y.w;
    }
    if (p1 >= 0) {
        float4 y = yb[(size_t)p1 * 64 + c4];
        r.x += s1 * y.x; r.y += s1 * y.y; r.z += s1 * y.z; r.w += s1 * y.w;
    }
    ((float4*)out)[idx] = r;
}

// ---------------- aux loss ---------------------------------------------------
__global__ __launch_bounds__(256) void k_loadsum() {
    __shared__ float sh[256];
    int e = blockIdx.x;
    float s = 0.0f;
    for (int b = threadIdx.x; b < NB2; b += 256) s += g_gatesum[(size_t)b * 64 + e];
    sh[threadIdx.x] = s;
    __syncthreads();
    for (int o = 128; o; o >>= 1) {
        if (threadIdx.x < o) sh[threadIdx.x] += sh[threadIdx.x + o];
        __syncthreads();
    }
    if (threadIdx.x == 0) g_load[e] = sh[0];
}

__global__ void k_aux(float* __restrict__ out, int out_size) {
    __shared__ float sh[64];
    int e = threadIdx.x;
    float load = g_load[e] / (float)N_TOK;
    float d = load - (1.0f / 64.0f);
    sh[e] = d * d;
    __syncthreads();
    for (int o = 32; o; o >>= 1) {
        if (e < o) sh[e] += sh[e + o];
        __syncthreads();
    }
    if (e == 0 && out_size > N_TOK * C_DIM) out[N_TOK * C_DIM] = sh[0] / 64.0f;
}

// ---------------- launch ----------------------------------------------------
extern "C" void kernel_launch(void* const* d_in, const int* in_sizes, int n_in,
                              void* d_out, int out_size) {
    const float* x  = (const float*)d_in[0];
    const float* wg = (const float*)d_in[1];
    const float* we = (const float*)d_in[2];
    float* out = (float*)d_out;

    static int s_init = 0;
    if (!s_init) {
        cudaFuncSetAttribute(k_gemm_hmma, cudaFuncAttributeMaxDynamicSharedMemorySize, GM_SMEM);
        s_init = 1;
    }

    k_convert_x <<<16384, 256>>>(x);
    k_convert_wt<<<dim3(8, 8, 64), dim3(32, 8)>>>(we);
    k_logits    <<<512, 256>>>(x, wg);
    k_router    <<<NB2, 256>>>();
    k_hist      <<<NCHUNK, 256>>>();
    k_scan      <<<E_NUM, 128>>>();
    k_rank      <<<NCHUNK, 1024>>>();
    k_gemm_hmma <<<dim3(CAPACITY / 128, 2, E_NUM), 256, GM_SMEM>>>();
    k_combine   <<<N_TOK / 4, 256>>>(out);
    k_loadsum   <<<E_NUM, 256>>>();
    k_aux       <<<1, 64>>>(out, out_size);
}

// round 4
// speedup vs baseline: 1.8417x; 1.3225x over previous
#include <cuda_runtime.h>
#include <cuda_bf16.h>
#include <math.h>
#include <stdint.h>

#define N_TOK    65536
#define C_DIM    256
#define E_NUM    64
#define S_SLOTS  131072
#define CAPACITY 2560
#define NCHUNK   128      /* S_SLOTS / 1024 */
#define NB2      8192     /* N_TOK / 8 router blocks */

// ---------------- scratch (device globals; no allocations) ----------------
__device__ float g_logits[N_TOK * E_NUM];
__device__ int   g_eid[S_SLOTS];
__device__ float g_sc[S_SLOTS];
__device__ int   g_pos[S_SLOTS];
__device__ int   g_hist[NCHUNK * E_NUM];
__device__ int   g_chunkbase[NCHUNK * E_NUM];
__device__ int   g_kept[E_NUM];
__device__ int   g_tok[E_NUM * CAPACITY];
__device__ float g_ybuf[(size_t)E_NUM * CAPACITY * C_DIM];
__device__ float g_gatesum[NB2 * E_NUM];
__device__ float g_load[E_NUM];
// bf16 hi/lo splits
__device__ __nv_bfloat16 g_xhi[(size_t)N_TOK * C_DIM];
__device__ __nv_bfloat16 g_xlo[(size_t)N_TOK * C_DIM];
__device__ __nv_bfloat16 g_wthi[(size_t)E_NUM * C_DIM * C_DIM];  // [e][n][k]
__device__ __nv_bfloat16 g_wtlo[(size_t)E_NUM * C_DIM * C_DIM];

// ---------------- packed fp32x2 helpers -------------------------------------
__device__ __forceinline__ unsigned long long splat2(float x) {
    unsigned long long r;
    asm("mov.b64 %0, {%1, %1};" : "=l"(r) : "f"(x));
    return r;
}
__device__ __forceinline__ void fma2(unsigned long long& d, unsigned long long a,
                                     unsigned long long b) {
    asm("fma.rn.f32x2 %0, %1, %2, %0;" : "+l"(d) : "l"(a), "l"(b));
}
__device__ __forceinline__ float lo2(unsigned long long v) { return __uint_as_float((unsigned)v); }
__device__ __forceinline__ float hi2(unsigned long long v) { return __uint_as_float((unsigned)(v >> 32)); }

// ---------------- mma.sync / cp.async helpers (base sm_103-safe) ------------
__device__ __forceinline__ uint32_t smem_u32(const void* p) {
    uint32_t a;
    asm("{ .reg .u64 t; cvta.to.shared.u64 t, %1; cvt.u32.u64 %0, t; }"
        : "=r"(a) : "l"(p));
    return a;
}
__device__ __forceinline__ void ldsm_x4(uint32_t* r, uint32_t a) {
    asm volatile("ldmatrix.sync.aligned.m8n8.x4.shared.b16 {%0,%1,%2,%3}, [%4];"
                 : "=r"(r[0]), "=r"(r[1]), "=r"(r[2]), "=r"(r[3]) : "r"(a));
}
__device__ __forceinline__ void ldsm_x2(uint32_t* r, uint32_t a) {
    asm volatile("ldmatrix.sync.aligned.m8n8.x2.shared.b16 {%0,%1}, [%2];"
                 : "=r"(r[0]), "=r"(r[1]) : "r"(a));
}
__device__ __forceinline__ void mma_bf16(float* d, const uint32_t* a, const uint32_t* b) {
    asm volatile(
        "mma.sync.aligned.m16n8k16.row.col.f32.bf16.bf16.f32 "
        "{%0,%1,%2,%3}, {%4,%5,%6,%7}, {%8,%9}, {%0,%1,%2,%3};"
        : "+f"(d[0]), "+f"(d[1]), "+f"(d[2]), "+f"(d[3])
        : "r"(a[0]), "r"(a[1]), "r"(a[2]), "r"(a[3]), "r"(b[0]), "r"(b[1]));
}
__device__ __forceinline__ void cpa16(uint32_t dst, const void* src, int bytes) {
    asm volatile("cp.async.cg.shared.global [%0], [%1], 16, %2;"
                 :: "r"(dst), "l"(src), "r"(bytes));
}
#define CP_COMMIT() asm volatile("cp.async.commit_group;" ::: "memory")
#define CP_WAIT(n)  asm volatile("cp.async.wait_group %0;" :: "n"(n) : "memory")

// ---------------- K1: logits = x @ W_gate -----------------------------------
__global__ __launch_bounds__(256, 2) void k_logits(const float* __restrict__ x,
                                                   const float* __restrict__ wg) {
    __shared__ float As[16][132];
    __shared__ float Bs[16][68];
    int tid = threadIdx.x;
    int tx = tid & 15, ty = tid >> 4;
    int row0 = blockIdx.x * 128;

    unsigned long long acc[8][2];
#pragma unroll
    for (int i = 0; i < 8; i++) { acc[i][0] = 0ULL; acc[i][1] = 0ULL; }

    const float4* x4 = (const float4*)x;
    const float4* w4 = (const float4*)wg;

    for (int kb = 0; kb < 16; kb++) {
        for (int l = tid; l < 512; l += 256) {
            int m = l >> 2, cs = l & 3;
            float4 v = x4[(size_t)(row0 + m) * 64 + kb * 4 + cs];
            As[cs * 4 + 0][m] = v.x; As[cs * 4 + 1][m] = v.y;
            As[cs * 4 + 2][m] = v.z; As[cs * 4 + 3][m] = v.w;
        }
        {
            int kk = tid >> 4, n4 = tid & 15;
            float4 v = w4[(size_t)(kb * 16 + kk) * 16 + n4];
            *(float4*)&Bs[kk][n4 * 4] = v;
        }
        __syncthreads();
#pragma unroll
        for (int kk = 0; kk < 16; kk++) {
            ulonglong2 bb = *(const ulonglong2*)&Bs[kk][tx * 4];
            float a[8];
            *(float4*)&a[0] = *(const float4*)&As[kk][ty * 8];
            *(float4*)&a[4] = *(const float4*)&As[kk][ty * 8 + 4];
#pragma unroll
            for (int i = 0; i < 8; i++) {
                unsigned long long s = splat2(a[i]);
                fma2(acc[i][0], s, bb.x);
                fma2(acc[i][1], s, bb.y);
            }
        }
        __syncthreads();
    }
#pragma unroll
    for (int i = 0; i < 8; i++) {
        int r = row0 + ty * 8 + i;
        float4 o;
        o.x = lo2(acc[i][0]); o.y = hi2(acc[i][0]);
        o.z = lo2(acc[i][1]); o.w = hi2(acc[i][1]);
        ((float4*)g_logits)[(size_t)r * 16 + tx] = o;
    }
}

// ---------------- K2: softmax + top-2 ---------------------------------------
__global__ __launch_bounds__(256) void k_router() {
    __shared__ float sg[8][64];
    int tid = threadIdx.x, lane = tid & 31, w = tid >> 5;
    int tok = blockIdx.x * 8 + w;
    const float* lg = g_logits + (size_t)tok * 64;
    float v0 = lg[lane], v1 = lg[lane + 32];

    float mx = fmaxf(v0, v1);
#pragma unroll
    for (int o = 16; o; o >>= 1) mx = fmaxf(mx, __shfl_xor_sync(0xffffffffu, mx, o));
    float e0 = expf(v0 - mx), e1 = expf(v1 - mx);
    float sum = e0 + e1;
#pragma unroll
    for (int o = 16; o; o >>= 1) sum += __shfl_xor_sync(0xffffffffu, sum, o);
    float g0 = e0 / sum, g1 = e1 / sum;

    float bv; int bi;
    if (v1 > v0) { bv = v1; bi = lane + 32; } else { bv = v0; bi = lane; }
#pragma unroll
    for (int o = 16; o; o >>= 1) {
        float ov = __shfl_xor_sync(0xffffffffu, bv, o);
        int   oi = __shfl_xor_sync(0xffffffffu, bi, o);
        if (ov > bv || (ov == bv && oi < bi)) { bv = ov; bi = oi; }
    }
    int i1 = bi;

    const float NEG = __int_as_float(0xff800000);
    float w0 = (lane == i1) ? NEG : v0;
    float w1 = (lane + 32 == i1) ? NEG : v1;
    float cv; int ci;
    if (w1 > w0) { cv = w1; ci = lane + 32; } else { cv = w0; ci = lane; }
#pragma unroll
    for (int o = 16; o; o >>= 1) {
        float ov = __shfl_xor_sync(0xffffffffu, cv, o);
        int   oi = __shfl_xor_sync(0xffffffffu, ci, o);
        if (ov > cv || (ov == cv && oi < ci)) { cv = ov; ci = oi; }
    }
    int i2 = ci;

    float s1 = __shfl_sync(0xffffffffu, (i1 < 32) ? g0 : g1, i1 & 31);
    float s2 = __shfl_sync(0xffffffffu, (i2 < 32) ? g0 : g1, i2 & 31);

    if (lane == 0) {
        g_eid[2 * tok] = i1;     g_sc[2 * tok] = s1;
        g_eid[2 * tok + 1] = i2; g_sc[2 * tok + 1] = s2;
    }
    sg[w][lane] = g0; sg[w][lane + 32] = g1;
    __syncthreads();
    if (tid < 64) {
        float s = 0.0f;
#pragma unroll
        for (int j = 0; j < 8; j++) s += sg[j][tid];
        g_gatesum[(size_t)blockIdx.x * 64 + tid] = s;
    }
}

// ---------------- K3: per-chunk expert histograms ---------------------------
__global__ __launch_bounds__(256) void k_hist() {
    __shared__ int h[64];
    int tid = threadIdx.x;
    if (tid < 64) h[tid] = 0;
    __syncthreads();
    int base = blockIdx.x * 1024;
#pragma unroll
    for (int j = 0; j < 4; j++) atomicAdd(&h[g_eid[base + j * 256 + tid]], 1);
    __syncthreads();
    if (tid < 64) g_hist[blockIdx.x * 64 + tid] = h[tid];
}

// ---------------- K4: parallel exclusive scan per expert --------------------
__global__ __launch_bounds__(128) void k_scan() {
    __shared__ int s[128];
    int e = blockIdx.x, t = threadIdx.x;
    int v = g_hist[t * 64 + e];
    s[t] = v;
    __syncthreads();
#pragma unroll
    for (int o = 1; o < 128; o <<= 1) {
        int x = (t >= o) ? s[t - o] : 0;
        __syncthreads();
        s[t] += x;
        __syncthreads();
    }
    g_chunkbase[t * 64 + e] = s[t] - v;
    if (t == 127) g_kept[e] = (s[127] < CAPACITY) ? s[127] : CAPACITY;
}

// ---------------- K5: FIFO ranks via warp ballots ---------------------------
__global__ __launch_bounds__(1024) void k_rank() {
    __shared__ int whist[32][64];
    int t = threadIdx.x, lane = t & 31, w = t >> 5;
    int slot = blockIdx.x * 1024 + t;
    int e = g_eid[slot];
    ((int*)whist)[t] = 0;
    ((int*)whist)[t + 1024] = 0;
    __syncthreads();
    unsigned peers = __match_any_sync(0xffffffffu, e);
    int lr = __popc(peers & ((1u << lane) - 1u));
    if (lr == 0) whist[w][e] = __popc(peers);
    __syncthreads();
    int base = g_chunkbase[blockIdx.x * 64 + e];
    for (int j = 0; j < w; j++) base += whist[j][e];
    int rank = base + lr;
    if (rank < CAPACITY) {
        int p = e * CAPACITY + rank;
        g_pos[slot] = p;
        g_tok[p] = slot >> 1;
    } else {
        g_pos[slot] = -1;
    }
}

// ---------------- K_cvx: x -> bf16 hi/lo ------------------------------------
__global__ __launch_bounds__(256) void k_convert_x(const float* __restrict__ x) {
    size_t i = (size_t)blockIdx.x * 256 + threadIdx.x;
    float4 v = ((const float4*)x)[i];
    float f[4] = {v.x, v.y, v.z, v.w};
    unsigned short h[4], l[4];
#pragma unroll
    for (int j = 0; j < 4; j++) {
        __nv_bfloat16 hb = __float2bfloat16_rn(f[j]);
        __nv_bfloat16 lb = __float2bfloat16_rn(f[j] - __bfloat162float(hb));
        h[j] = __bfloat16_as_ushort(hb);
        l[j] = __bfloat16_as_ushort(lb);
    }
    uint2 ph, pl;
    ph.x = (unsigned)h[0] | ((unsigned)h[1] << 16);
    ph.y = (unsigned)h[2] | ((unsigned)h[3] << 16);
    pl.x = (unsigned)l[0] | ((unsigned)l[1] << 16);
    pl.y = (unsigned)l[2] | ((unsigned)l[3] << 16);
    ((uint2*)g_xhi)[i] = ph;
    ((uint2*)g_xlo)[i] = pl;
}

// ---------------- K_cvw: W_e[k][n] -> Wt[e][n][k] bf16 hi/lo ----------------
__global__ void k_convert_wt(const float* __restrict__ we) {
    __shared__ float ts[32][33];
    int e = blockIdx.z, kt = blockIdx.y, nt = blockIdx.x;
    int tx = threadIdx.x, ty = threadIdx.y;  // (32,8)
    const float* src = we + ((size_t)e * 256 + (size_t)kt * 32) * 256 + nt * 32;
#pragma unroll
    for (int j = 0; j < 32; j += 8) ts[ty + j][tx] = src[(size_t)(ty + j) * 256 + tx];
    __syncthreads();
#pragma unroll
    for (int j = 0; j < 32; j += 8) {
        float vv = ts[tx][ty + j];
        __nv_bfloat16 hb = __float2bfloat16_rn(vv);
        __nv_bfloat16 lb = __float2bfloat16_rn(vv - __bfloat162float(hb));
        size_t d = ((size_t)e * 256 + (size_t)nt * 32 + ty + j) * 256 + kt * 32 + tx;
        g_wthi[d] = hb;
        g_wtlo[d] = lb;
    }
}

// ---------------- K6: grouped GEMM on HMMA, cp.async double-buffered --------
// CTA: 128 gathered rows x 128 cols, K=256 in 4 chunks of 64.
// 8 warps, warp tile 64x32 (4 m-tiles x 4 n-tiles of m16n8k16).
// Per-stage SMEM: AH, AL, BH, BL, each 128 rows x 64 bf16 @ 144B pitch.
#define TB       (128 * 144)              /* 18432 B per tile */
#define ST_AH    0
#define ST_AL    (TB)
#define ST_BH    (2 * TB)
#define ST_BL    (3 * TB)
#define STAGE    (4 * TB)                 /* 73728 B */
#define OFF_TOK  (2 * STAGE)
#define GM_SMEM  (2 * STAGE + 512)        /* 147968 B */

__global__ __launch_bounds__(256, 1) void k_gemm_hmma() {
    extern __shared__ char sm[];
    const uint32_t smb = smem_u32(sm);
    int tid = threadIdx.x, lane = tid & 31, wid = tid >> 5;

    int e = blockIdx.z;
    int kept = g_kept[e];
    int m0 = blockIdx.x * 128;
    if (m0 >= kept) return;
    int n0 = blockIdx.y * 128;

    int* stok = (int*)(sm + OFF_TOK);
    if (tid < 128) {
        int r = m0 + tid;
        stok[tid] = (r < kept) ? g_tok[e * CAPACITY + r] : -1;
    }
    __syncthreads();

    const uint4* xh4 = (const uint4*)g_xhi;
    const uint4* xl4 = (const uint4*)g_xlo;
    const uint4* wh4 = (const uint4*)g_wthi;
    const uint4* wl4 = (const uint4*)g_wtlo;

    // per-thread load coordinates: 4 (row,c8) pairs covering 128x8 vectors
    int lrow[4], lc8[4];
    const uint4* asrc_h[4];
    const uint4* asrc_l[4];
    int abytes[4];
#pragma unroll
    for (int j = 0; j < 4; j++) {
        int idx = j * 256 + tid;
        lrow[j] = idx >> 3;
        lc8[j] = idx & 7;
        int tk = stok[lrow[j]];
        int ok = tk >= 0;
        int tkc = ok ? tk : 0;
        asrc_h[j] = xh4 + (size_t)tkc * 32 + lc8[j];
        asrc_l[j] = xl4 + (size_t)tkc * 32 + lc8[j];
        abytes[j] = ok ? 16 : 0;
    }
    const uint4* bsrc_h[4];
    const uint4* bsrc_l[4];
#pragma unroll
    for (int j = 0; j < 4; j++) {
        bsrc_h[j] = wh4 + (size_t)(e * 256 + n0 + lrow[j]) * 32 + lc8[j];
        bsrc_l[j] = wl4 + (size_t)(e * 256 + n0 + lrow[j]) * 32 + lc8[j];
    }

    // issue loads for chunk kc into stage s (s in {0,1})
    auto load_stage = [&](int kc, int s) {
        uint32_t sb = smb + s * STAGE;
        int koff = kc * 8;   // uint4 offset within row
#pragma unroll
        for (int j = 0; j < 4; j++) {
            uint32_t o = (uint32_t)(lrow[j] * 144 + lc8[j] * 16);
            cpa16(sb + ST_AH + o, asrc_h[j] + koff, abytes[j]);
            cpa16(sb + ST_AL + o, asrc_l[j] + koff, abytes[j]);
            cpa16(sb + ST_BH + o, bsrc_h[j] + koff, 16);
            cpa16(sb + ST_BL + o, bsrc_l[j] + koff, 16);
        }
    };

    int wm = wid >> 2, wn = wid & 3;

    float acc[4][4][4];
#pragma unroll
    for (int mt = 0; mt < 4; mt++)
#pragma unroll
        for (int nt = 0; nt < 4; nt++)
#pragma unroll
            for (int q = 0; q < 4; q++) acc[mt][nt][q] = 0.0f;

    int a_m = lane >> 3, a_r = lane & 7;
    int b_l = lane & 15;

    load_stage(0, 0);
    CP_COMMIT();

#pragma unroll
    for (int kc = 0; kc < 4; kc++) {
        if (kc < 3) {
            load_stage(kc + 1, (kc + 1) & 1);
            CP_COMMIT();
            CP_WAIT(1);
        } else {
            CP_WAIT(0);
        }
        __syncthreads();

        uint32_t base = smb + (kc & 1) * STAGE;
#pragma unroll
        for (int ks = 0; ks < 4; ks++) {
            int k0 = ks * 16;
            uint32_t ah[4][4], al[4][4], bh[4][2], bl[4][2];
#pragma unroll
            for (int mt = 0; mt < 4; mt++) {
                int arow = wm * 64 + mt * 16 + (a_m & 1) * 8 + a_r;
                int acol = k0 + (a_m >> 1) * 8;
                uint32_t off = (uint32_t)(arow * 144 + acol * 2);
                ldsm_x4(ah[mt], base + ST_AH + off);
                ldsm_x4(al[mt], base + ST_AL + off);
            }
#pragma unroll
            for (int nt = 0; nt < 4; nt++) {
                int brow = wn * 32 + nt * 8 + (b_l & 7);
                int bcol = k0 + ((b_l >> 3) & 1) * 8;
                uint32_t off = (uint32_t)(brow * 144 + bcol * 2);
                ldsm_x2(bh[nt], base + ST_BH + off);
                ldsm_x2(bl[nt], base + ST_BL + off);
            }
#pragma unroll
            for (int mt = 0; mt < 4; mt++)
#pragma unroll
                for (int nt = 0; nt < 4; nt++) {
                    mma_bf16(acc[mt][nt], ah[mt], bh[nt]);
                    mma_bf16(acc[mt][nt], ah[mt], bl[nt]);
                    mma_bf16(acc[mt][nt], al[mt], bh[nt]);
                }
        }
        __syncthreads();
    }

    // ---- epilogue: stage through SMEM for coalesced stores ----
    float* fb = (float*)sm;                      // [128][132]
    int g = lane >> 2, c = lane & 3;
#pragma unroll
    for (int mt = 0; mt < 4; mt++) {
#pragma unroll
        for (int nt = 0; nt < 4; nt++) {
            int row = wm * 64 + mt * 16 + g;
            int col = wn * 32 + nt * 8 + c * 2;
            float2 v0 = make_float2(acc[mt][nt][0], acc[mt][nt][1]);
            float2 v1 = make_float2(acc[mt][nt][2], acc[mt][nt][3]);
            *(float2*)&fb[row * 132 + col] = v0;
            *(float2*)&fb[(row + 8) * 132 + col] = v1;
        }
    }
    __syncthreads();
    int c4 = tid & 31;
#pragma unroll
    for (int rp = 0; rp < 16; rp++) {
        int row = rp * 8 + (tid >> 5);
        if (m0 + row < kept) {
            float4 v = *(const float4*)&fb[row * 132 + c4 * 4];
            *(float4*)(g_ybuf + ((size_t)e * CAPACITY + m0 + row) * 256 + n0 + c4 * 4) = v;
        }
    }
}

// ---------------- K_combine --------------------------------------------------
__global__ __launch_bounds__(256) void k_combine(float* __restrict__ out) {
    int idx = blockIdx.x * 256 + threadIdx.x;
    int tok = idx >> 6, c4 = idx & 63;
    int p0 = g_pos[2 * tok], p1 = g_pos[2 * tok + 1];
    float s0 = g_sc[2 * tok], s1 = g_sc[2 * tok + 1];
    float4 r = make_float4(0.f, 0.f, 0.f, 0.f);
    const float4* yb = (const float4*)g_ybuf;
    if (p0 >= 0) {
        float4 y = yb[(size_t)p0 * 64 + c4];
        r.x = s0 * y.x; r.y = s0 * y.y; r.z = s0 * y.z; r.w = s0 * y.w;
    }
    if (p1 >= 0) {
        float4 y = yb[(size_t)p1 * 64 + c4];
        r.x += s1 * y.x; r.y += s1 * y.y; r.z += s1 * y.z; r.w += s1 * y.w;
    }
    ((float4*)out)[idx] = r;
}

// ---------------- aux loss ---------------------------------------------------
__global__ __launch_bounds__(256) void k_loadsum() {
    __shared__ float sh[256];
    int e = blockIdx.x;
    float s = 0.0f;
    for (int b = threadIdx.x; b < NB2; b += 256) s += g_gatesum[(size_t)b * 64 + e];
    sh[threadIdx.x] = s;
    __syncthreads();
    for (int o = 128; o; o >>= 1) {
        if (threadIdx.x < o) sh[threadIdx.x] += sh[threadIdx.x + o];
        __syncthreads();
    }
    if (threadIdx.x == 0) g_load[e] = sh[0];
}

__global__ void k_aux(float* __restrict__ out, int out_size) {
    __shared__ float sh[64];
    int e = threadIdx.x;
    float load = g_load[e] / (float)N_TOK;
    float d = load - (1.0f / 64.0f);
    sh[e] = d * d;
    __syncthreads();
    for (int o = 32; o; o >>= 1) {
        if (e < o) sh[e] += sh[e + o];
        __syncthreads();
    }
    if (e == 0 && out_size > N_TOK * C_DIM) out[N_TOK * C_DIM] = sh[0] / 64.0f;
}

// ---------------- launch ----------------------------------------------------
extern "C" void kernel_launch(void* const* d_in, const int* in_sizes, int n_in,
                              void* d_out, int out_size) {
    const float* x  = (const float*)d_in[0];
    const float* wg = (const float*)d_in[1];
    const float* we = (const float*)d_in[2];
    float* out = (float*)d_out;

    cudaFuncSetAttribute(k_gemm_hmma, cudaFuncAttributeMaxDynamicSharedMemorySize, GM_SMEM);

    k_convert_x <<<16384, 256>>>(x);
    k_convert_wt<<<dim3(8, 8, 64), dim3(32, 8)>>>(we);
    k_logits    <<<512, 256>>>(x, wg);
    k_router    <<<NB2, 256>>>();
    k_hist      <<<NCHUNK, 256>>>();
    k_scan      <<<E_NUM, 128>>>();
    k_rank      <<<NCHUNK, 1024>>>();
    k_gemm_hmma <<<dim3(CAPACITY / 128, 2, E_NUM), 256, GM_SMEM>>>();
    k_combine   <<<N_TOK / 4, 256>>>(out);
    k_loadsum   <<<E_NUM, 256>>>();
    k_aux       <<<1, 64>>>(out, out_size);
}

// round 5
// speedup vs baseline: 1.9047x; 1.0342x over previous
#include <cuda_runtime.h>
#include <cuda_bf16.h>
#include <math.h>
#include <stdint.h>

#define N_TOK    65536
#define C_DIM    256
#define E_NUM    64
#define S_SLOTS  131072
#define CAPACITY 2560
#define NCHUNK   128      /* S_SLOTS / 1024 */
#define NBF      512      /* front-end blocks (128 tokens each) */

// ---------------- scratch (device globals; no allocations) ----------------
__device__ int   g_eid[S_SLOTS];
__device__ float g_sc[S_SLOTS];
__device__ int   g_pos[S_SLOTS];
__device__ int   g_hist[NCHUNK * E_NUM];
__device__ int   g_chunkbase[NCHUNK * E_NUM];
__device__ int   g_kept[E_NUM];
__device__ int   g_tok[E_NUM * CAPACITY];
__device__ float g_ybuf[(size_t)E_NUM * CAPACITY * C_DIM];
__device__ float g_gatesum[NBF * E_NUM];
__device__ float g_load[E_NUM];
// bf16 hi/lo splits
__device__ __nv_bfloat16 g_xhi[(size_t)N_TOK * C_DIM];
__device__ __nv_bfloat16 g_xlo[(size_t)N_TOK * C_DIM];
__device__ __nv_bfloat16 g_wthi[(size_t)E_NUM * C_DIM * C_DIM];  // [e][n][k]
__device__ __nv_bfloat16 g_wtlo[(size_t)E_NUM * C_DIM * C_DIM];

// ---------------- packed fp32x2 helpers -------------------------------------
__device__ __forceinline__ unsigned long long splat2(float x) {
    unsigned long long r;
    asm("mov.b64 %0, {%1, %1};" : "=l"(r) : "f"(x));
    return r;
}
__device__ __forceinline__ void fma2(unsigned long long& d, unsigned long long a,
                                     unsigned long long b) {
    asm("fma.rn.f32x2 %0, %1, %2, %0;" : "+l"(d) : "l"(a), "l"(b));
}
__device__ __forceinline__ float lo2(unsigned long long v) { return __uint_as_float((unsigned)v); }
__device__ __forceinline__ float hi2(unsigned long long v) { return __uint_as_float((unsigned)(v >> 32)); }

// ---------------- mma.sync / cp.async helpers (base sm_103-safe) ------------
__device__ __forceinline__ uint32_t smem_u32(const void* p) {
    uint32_t a;
    asm("{ .reg .u64 t; cvta.to.shared.u64 t, %1; cvt.u32.u64 %0, t; }"
        : "=r"(a) : "l"(p));
    return a;
}
__device__ __forceinline__ void ldsm_x4(uint32_t* r, uint32_t a) {
    asm volatile("ldmatrix.sync.aligned.m8n8.x4.shared.b16 {%0,%1,%2,%3}, [%4];"
                 : "=r"(r[0]), "=r"(r[1]), "=r"(r[2]), "=r"(r[3]) : "r"(a));
}
__device__ __forceinline__ void ldsm_x2(uint32_t* r, uint32_t a) {
    asm volatile("ldmatrix.sync.aligned.m8n8.x2.shared.b16 {%0,%1}, [%2];"
                 : "=r"(r[0]), "=r"(r[1]) : "r"(a));
}
__device__ __forceinline__ void mma_bf16(float* d, const uint32_t* a, const uint32_t* b) {
    asm volatile(
        "mma.sync.aligned.m16n8k16.row.col.f32.bf16.bf16.f32 "
        "{%0,%1,%2,%3}, {%4,%5,%6,%7}, {%8,%9}, {%0,%1,%2,%3};"
        : "+f"(d[0]), "+f"(d[1]), "+f"(d[2]), "+f"(d[3])
        : "r"(a[0]), "r"(a[1]), "r"(a[2]), "r"(a[3]), "r"(b[0]), "r"(b[1]));
}
__device__ __forceinline__ void cpa16(uint32_t dst, const void* src, int bytes) {
    asm volatile("cp.async.cg.shared.global [%0], [%1], 16, %2;"
                 :: "r"(dst), "l"(src), "r"(bytes));
}
#define CP_COMMIT() asm volatile("cp.async.commit_group;" ::: "memory")
#define CP_WAIT(n)  asm volatile("cp.async.wait_group %0;" :: "n"(n) : "memory")

// ---------------- K_front: convert x + logits + softmax/top2 (fused) --------
// 512 blocks x 128 tokens. Logits via FFMA2 (identical math to r4), kept in
// SMEM; router runs in-block. x is read once; hi/lo conversion stored inline.
__global__ __launch_bounds__(256, 2) void k_front(const float* __restrict__ x,
                                                  const float* __restrict__ wg) {
    __shared__ char smbuf[34816];            // overlay: tiles then logits
    __shared__ float gs[8][64];
    float (*As)[132] = (float(*)[132])smbuf;           // 16x132 = 8448 B
    float (*Bs)[68]  = (float(*)[68])(smbuf + 8448);   // 16x68  = 4352 B
    float (*lgt)[68] = (float(*)[68])smbuf;            // 128x68 = 34816 B

    int tid = threadIdx.x, lane = tid & 31, w = tid >> 5;
    int tx = tid & 15, ty = tid >> 4;
    int row0 = blockIdx.x * 128;

    unsigned long long acc[8][2];
#pragma unroll
    for (int i = 0; i < 8; i++) { acc[i][0] = 0ULL; acc[i][1] = 0ULL; }

    const float4* x4 = (const float4*)x;
    const float4* w4 = (const float4*)wg;

    for (int kb = 0; kb < 16; kb++) {
        for (int l = tid; l < 512; l += 256) {
            int m = l >> 2, cs = l & 3;
            size_t gi = (size_t)(row0 + m) * 64 + kb * 4 + cs;
            float4 v = x4[gi];
            As[cs * 4 + 0][m] = v.x; As[cs * 4 + 1][m] = v.y;
            As[cs * 4 + 2][m] = v.z; As[cs * 4 + 3][m] = v.w;
            // inline hi/lo conversion store
            float f[4] = {v.x, v.y, v.z, v.w};
            unsigned short hh[4], ll[4];
#pragma unroll
            for (int j = 0; j < 4; j++) {
                __nv_bfloat16 hb = __float2bfloat16_rn(f[j]);
                __nv_bfloat16 lb = __float2bfloat16_rn(f[j] - __bfloat162float(hb));
                hh[j] = __bfloat16_as_ushort(hb);
                ll[j] = __bfloat16_as_ushort(lb);
            }
            uint2 ph, pl;
            ph.x = (unsigned)hh[0] | ((unsigned)hh[1] << 16);
            ph.y = (unsigned)hh[2] | ((unsigned)hh[3] << 16);
            pl.x = (unsigned)ll[0] | ((unsigned)ll[1] << 16);
            pl.y = (unsigned)ll[2] | ((unsigned)ll[3] << 16);
            ((uint2*)g_xhi)[gi] = ph;
            ((uint2*)g_xlo)[gi] = pl;
        }
        {
            int kk = tid >> 4, n4 = tid & 15;
            float4 v = w4[(size_t)(kb * 16 + kk) * 16 + n4];
            *(float4*)&Bs[kk][n4 * 4] = v;
        }
        __syncthreads();
#pragma unroll
        for (int kk = 0; kk < 16; kk++) {
            ulonglong2 bb = *(const ulonglong2*)&Bs[kk][tx * 4];
            float a[8];
            *(float4*)&a[0] = *(const float4*)&As[kk][ty * 8];
            *(float4*)&a[4] = *(const float4*)&As[kk][ty * 8 + 4];
#pragma unroll
            for (int i = 0; i < 8; i++) {
                unsigned long long s = splat2(a[i]);
                fma2(acc[i][0], s, bb.x);
                fma2(acc[i][1], s, bb.y);
            }
        }
        __syncthreads();
    }

    // stash logits into SMEM (overlay on dead tiles)
#pragma unroll
    for (int i = 0; i < 8; i++) {
        float4 o;
        o.x = lo2(acc[i][0]); o.y = hi2(acc[i][0]);
        o.z = lo2(acc[i][1]); o.w = hi2(acc[i][1]);
        *(float4*)&lgt[ty * 8 + i][tx * 4] = o;
    }
    __syncthreads();

    // router: each warp handles 16 tokens
    float gsum_lo = 0.0f, gsum_hi = 0.0f;
    const float NEG = __int_as_float(0xff800000);
#pragma unroll 1
    for (int it = 0; it < 16; it++) {
        int t = w * 16 + it;
        float v0 = lgt[t][lane], v1 = lgt[t][lane + 32];

        float mx = fmaxf(v0, v1);
#pragma unroll
        for (int o = 16; o; o >>= 1) mx = fmaxf(mx, __shfl_xor_sync(0xffffffffu, mx, o));
        float e0 = expf(v0 - mx), e1 = expf(v1 - mx);
        float sum = e0 + e1;
#pragma unroll
        for (int o = 16; o; o >>= 1) sum += __shfl_xor_sync(0xffffffffu, sum, o);
        float g0 = e0 / sum, g1 = e1 / sum;
        gsum_lo += g0; gsum_hi += g1;

        float bv; int bi;
        if (v1 > v0) { bv = v1; bi = lane + 32; } else { bv = v0; bi = lane; }
#pragma unroll
        for (int o = 16; o; o >>= 1) {
            float ov = __shfl_xor_sync(0xffffffffu, bv, o);
            int   oi = __shfl_xor_sync(0xffffffffu, bi, o);
            if (ov > bv || (ov == bv && oi < bi)) { bv = ov; bi = oi; }
        }
        int i1 = bi;

        float w0 = (lane == i1) ? NEG : v0;
        float w1 = (lane + 32 == i1) ? NEG : v1;
        float cv; int ci;
        if (w1 > w0) { cv = w1; ci = lane + 32; } else { cv = w0; ci = lane; }
#pragma unroll
        for (int o = 16; o; o >>= 1) {
            float ov = __shfl_xor_sync(0xffffffffu, cv, o);
            int   oi = __shfl_xor_sync(0xffffffffu, ci, o);
            if (ov > cv || (ov == cv && oi < ci)) { cv = ov; ci = oi; }
        }
        int i2 = ci;

        float s1 = __shfl_sync(0xffffffffu, (i1 < 32) ? g0 : g1, i1 & 31);
        float s2 = __shfl_sync(0xffffffffu, (i2 < 32) ? g0 : g1, i2 & 31);

        if (lane == 0) {
            int tok = row0 + t;
            g_eid[2 * tok] = i1;     g_sc[2 * tok] = s1;
            g_eid[2 * tok + 1] = i2; g_sc[2 * tok + 1] = s2;
        }
    }
    gs[w][lane] = gsum_lo;
    gs[w][lane + 32] = gsum_hi;
    __syncthreads();
    if (tid < 64) {
        float s = 0.0f;
#pragma unroll
        for (int j = 0; j < 8; j++) s += gs[j][tid];
        g_gatesum[(size_t)blockIdx.x * 64 + tid] = s;
    }
}

// ---------------- K3: per-chunk expert histograms ---------------------------
__global__ __launch_bounds__(256) void k_hist() {
    __shared__ int h[64];
    int tid = threadIdx.x;
    if (tid < 64) h[tid] = 0;
    __syncthreads();
    int base = blockIdx.x * 1024;
#pragma unroll
    for (int j = 0; j < 4; j++) atomicAdd(&h[g_eid[base + j * 256 + tid]], 1);
    __syncthreads();
    if (tid < 64) g_hist[blockIdx.x * 64 + tid] = h[tid];
}

// ---------------- K4: parallel exclusive scan per expert --------------------
__global__ __launch_bounds__(128) void k_scan() {
    __shared__ int s[128];
    int e = blockIdx.x, t = threadIdx.x;
    int v = g_hist[t * 64 + e];
    s[t] = v;
    __syncthreads();
#pragma unroll
    for (int o = 1; o < 128; o <<= 1) {
        int x = (t >= o) ? s[t - o] : 0;
        __syncthreads();
        s[t] += x;
        __syncthreads();
    }
    g_chunkbase[t * 64 + e] = s[t] - v;
    if (t == 127) g_kept[e] = (s[127] < CAPACITY) ? s[127] : CAPACITY;
}

// ---------------- K5: FIFO ranks via warp ballots ---------------------------
__global__ __launch_bounds__(1024) void k_rank() {
    __shared__ int whist[32][64];
    int t = threadIdx.x, lane = t & 31, w = t >> 5;
    int slot = blockIdx.x * 1024 + t;
    int e = g_eid[slot];
    ((int*)whist)[t] = 0;
    ((int*)whist)[t + 1024] = 0;
    __syncthreads();
    unsigned peers = __match_any_sync(0xffffffffu, e);
    int lr = __popc(peers & ((1u << lane) - 1u));
    if (lr == 0) whist[w][e] = __popc(peers);
    __syncthreads();
    int base = g_chunkbase[blockIdx.x * 64 + e];
    for (int j = 0; j < w; j++) base += whist[j][e];
    int rank = base + lr;
    if (rank < CAPACITY) {
        int p = e * CAPACITY + rank;
        g_pos[slot] = p;
        g_tok[p] = slot >> 1;
    } else {
        g_pos[slot] = -1;
    }
}

// ---------------- K_cvw: W_e[k][n] -> Wt[e][n][k] bf16 hi/lo ----------------
__global__ void k_convert_wt(const float* __restrict__ we) {
    __shared__ float ts[32][33];
    int e = blockIdx.z, kt = blockIdx.y, nt = blockIdx.x;
    int tx = threadIdx.x, ty = threadIdx.y;  // (32,8)
    const float* src = we + ((size_t)e * 256 + (size_t)kt * 32) * 256 + nt * 32;
#pragma unroll
    for (int j = 0; j < 32; j += 8) ts[ty + j][tx] = src[(size_t)(ty + j) * 256 + tx];
    __syncthreads();
#pragma unroll
    for (int j = 0; j < 32; j += 8) {
        float vv = ts[tx][ty + j];
        __nv_bfloat16 hb = __float2bfloat16_rn(vv);
        __nv_bfloat16 lb = __float2bfloat16_rn(vv - __bfloat162float(hb));
        size_t d = ((size_t)e * 256 + (size_t)nt * 32 + ty + j) * 256 + kt * 32 + tx;
        g_wthi[d] = hb;
        g_wtlo[d] = lb;
    }
}

// ---------------- K6: grouped GEMM on HMMA, cp.async double-buffered --------
// CTA: 128 gathered rows x 128 cols, K=256 in 4 chunks of 64.
// 8 warps, warp tile 64x32. MMAs issued term-major: 3 passes of 16
// INDEPENDENT MMAs (no accumulator RAW chains).
#define TB       (128 * 144)              /* 18432 B per tile */
#define ST_AH    0
#define ST_AL    (TB)
#define ST_BH    (2 * TB)
#define ST_BL    (3 * TB)
#define STAGE    (4 * TB)                 /* 73728 B */
#define OFF_TOK  (2 * STAGE)
#define GM_SMEM  (2 * STAGE + 512)        /* 147968 B */

__global__ __launch_bounds__(256, 1) void k_gemm_hmma() {
    extern __shared__ char sm[];
    const uint32_t smb = smem_u32(sm);
    int tid = threadIdx.x, lane = tid & 31, wid = tid >> 5;

    int e = blockIdx.z;
    int kept = g_kept[e];
    int m0 = blockIdx.x * 128;
    if (m0 >= kept) return;
    int n0 = blockIdx.y * 128;

    int* stok = (int*)(sm + OFF_TOK);
    if (tid < 128) {
        int r = m0 + tid;
        stok[tid] = (r < kept) ? g_tok[e * CAPACITY + r] : -1;
    }
    __syncthreads();

    const uint4* xh4 = (const uint4*)g_xhi;
    const uint4* xl4 = (const uint4*)g_xlo;
    const uint4* wh4 = (const uint4*)g_wthi;
    const uint4* wl4 = (const uint4*)g_wtlo;

    int lrow[4], lc8[4];
    const uint4* asrc_h[4];
    const uint4* asrc_l[4];
    int abytes[4];
#pragma unroll
    for (int j = 0; j < 4; j++) {
        int idx = j * 256 + tid;
        lrow[j] = idx >> 3;
        lc8[j] = idx & 7;
        int tk = stok[lrow[j]];
        int ok = tk >= 0;
        int tkc = ok ? tk : 0;
        asrc_h[j] = xh4 + (size_t)tkc * 32 + lc8[j];
        asrc_l[j] = xl4 + (size_t)tkc * 32 + lc8[j];
        abytes[j] = ok ? 16 : 0;
    }
    const uint4* bsrc_h[4];
    const uint4* bsrc_l[4];
#pragma unroll
    for (int j = 0; j < 4; j++) {
        bsrc_h[j] = wh4 + (size_t)(e * 256 + n0 + lrow[j]) * 32 + lc8[j];
        bsrc_l[j] = wl4 + (size_t)(e * 256 + n0 + lrow[j]) * 32 + lc8[j];
    }

    auto load_stage = [&](int kc, int s) {
        uint32_t sb = smb + s * STAGE;
        int koff = kc * 8;
#pragma unroll
        for (int j = 0; j < 4; j++) {
            uint32_t o = (uint32_t)(lrow[j] * 144 + lc8[j] * 16);
            cpa16(sb + ST_AH + o, asrc_h[j] + koff, abytes[j]);
            cpa16(sb + ST_AL + o, asrc_l[j] + koff, abytes[j]);
            cpa16(sb + ST_BH + o, bsrc_h[j] + koff, 16);
            cpa16(sb + ST_BL + o, bsrc_l[j] + koff, 16);
        }
    };

    int wm = wid >> 2, wn = wid & 3;

    float acc[4][4][4];
#pragma unroll
    for (int mt = 0; mt < 4; mt++)
#pragma unroll
        for (int nt = 0; nt < 4; nt++)
#pragma unroll
            for (int q = 0; q < 4; q++) acc[mt][nt][q] = 0.0f;

    int a_m = lane >> 3, a_r = lane & 7;
    int b_l = lane & 15;

    load_stage(0, 0);
    CP_COMMIT();

#pragma unroll
    for (int kc = 0; kc < 4; kc++) {
        if (kc < 3) {
            load_stage(kc + 1, (kc + 1) & 1);
            CP_COMMIT();
            CP_WAIT(1);
        } else {
            CP_WAIT(0);
        }
        __syncthreads();

        uint32_t base = smb + (kc & 1) * STAGE;
#pragma unroll
        for (int ks = 0; ks < 4; ks++) {
            int k0 = ks * 16;
            uint32_t ah[4][4], al[4][4], bh[4][2], bl[4][2];
#pragma unroll
            for (int mt = 0; mt < 4; mt++) {
                int arow = wm * 64 + mt * 16 + (a_m & 1) * 8 + a_r;
                int acol = k0 + (a_m >> 1) * 8;
                uint32_t off = (uint32_t)(arow * 144 + acol * 2);
                ldsm_x4(ah[mt], base + ST_AH + off);
                ldsm_x4(al[mt], base + ST_AL + off);
            }
#pragma unroll
            for (int nt = 0; nt < 4; nt++) {
                int brow = wn * 32 + nt * 8 + (b_l & 7);
                int bcol = k0 + ((b_l >> 3) & 1) * 8;
                uint32_t off = (uint32_t)(brow * 144 + bcol * 2);
                ldsm_x2(bh[nt], base + ST_BH + off);
                ldsm_x2(bl[nt], base + ST_BL + off);
            }
            // term-major: 3 passes of 16 independent MMAs
#pragma unroll
            for (int mt = 0; mt < 4; mt++)
#pragma unroll
                for (int nt = 0; nt < 4; nt++)
                    mma_bf16(acc[mt][nt], ah[mt], bh[nt]);
#pragma unroll
            for (int mt = 0; mt < 4; mt++)
#pragma unroll
                for (int nt = 0; nt < 4; nt++)
                    mma_bf16(acc[mt][nt], ah[mt], bl[nt]);
#pragma unroll
            for (int mt = 0; mt < 4; mt++)
#pragma unroll
                for (int nt = 0; nt < 4; nt++)
                    mma_bf16(acc[mt][nt], al[mt], bh[nt]);
        }
        __syncthreads();
    }

    // ---- epilogue: stage through SMEM for coalesced stores ----
    float* fb = (float*)sm;                      // [128][132]
    int g = lane >> 2, c = lane & 3;
#pragma unroll
    for (int mt = 0; mt < 4; mt++) {
#pragma unroll
        for (int nt = 0; nt < 4; nt++) {
            int row = wm * 64 + mt * 16 + g;
            int col = wn * 32 + nt * 8 + c * 2;
            float2 v0 = make_float2(acc[mt][nt][0], acc[mt][nt][1]);
            float2 v1 = make_float2(acc[mt][nt][2], acc[mt][nt][3]);
            *(float2*)&fb[row * 132 + col] = v0;
            *(float2*)&fb[(row + 8) * 132 + col] = v1;
        }
    }
    __syncthreads();
    int c4 = tid & 31;
#pragma unroll
    for (int rp = 0; rp < 16; rp++) {
        int row = rp * 8 + (tid >> 5);
        if (m0 + row < kept) {
            float4 v = *(const float4*)&fb[row * 132 + c4 * 4];
            *(float4*)(g_ybuf + ((size_t)e * CAPACITY + m0 + row) * 256 + n0 + c4 * 4) = v;
        }
    }
}

// ---------------- K_combine --------------------------------------------------
__global__ __launch_bounds__(256) void k_combine(float* __restrict__ out) {
    int idx = blockIdx.x * 256 + threadIdx.x;
    int tok = idx >> 6, c4 = idx & 63;
    int p0 = g_pos[2 * tok], p1 = g_pos[2 * tok + 1];
    float s0 = g_sc[2 * tok], s1 = g_sc[2 * tok + 1];
    float4 r = make_float4(0.f, 0.f, 0.f, 0.f);
    const float4* yb = (const float4*)g_ybuf;
    if (p0 >= 0) {
        float4 y = yb[(size_t)p0 * 64 + c4];
        r.x = s0 * y.x; r.y = s0 * y.y; r.z = s0 * y.z; r.w = s0 * y.w;
    }
    if (p1 >= 0) {
        float4 y = yb[(size_t)p1 * 64 + c4];
        r.x += s1 * y.x; r.y += s1 * y.y; r.z += s1 * y.z; r.w += s1 * y.w;
    }
    ((float4*)out)[idx] = r;
}

// ---------------- aux loss ---------------------------------------------------
__global__ __launch_bounds__(256) void k_loadsum() {
    __shared__ float sh[256];
    int e = blockIdx.x;
    float s = 0.0f;
    for (int b = threadIdx.x; b < NBF; b += 256) s += g_gatesum[(size_t)b * 64 + e];
    sh[threadIdx.x] = s;
    __syncthreads();
    for (int o = 128; o; o >>= 1) {
        if (threadIdx.x < o) sh[threadIdx.x] += sh[threadIdx.x + o];
        __syncthreads();
    }
    if (threadIdx.x == 0) g_load[e] = sh[0];
}

__global__ void k_aux(float* __restrict__ out, int out_size) {
    __shared__ float sh[64];
    int e = threadIdx.x;
    float load = g_load[e] / (float)N_TOK;
    float d = load - (1.0f / 64.0f);
    sh[e] = d * d;
    __syncthreads();
    for (int o = 32; o; o >>= 1) {
        if (e < o) sh[e] += sh[e + o];
        __syncthreads();
    }
    if (e == 0 && out_size > N_TOK * C_DIM) out[N_TOK * C_DIM] = sh[0] / 64.0f;
}

// ---------------- launch ----------------------------------------------------
extern "C" void kernel_launch(void* const* d_in, const int* in_sizes, int n_in,
                              void* d_out, int out_size) {
    const float* x  = (const float*)d_in[0];
    const float* wg = (const float*)d_in[1];
    const float* we = (const float*)d_in[2];
    float* out = (float*)d_out;

    cudaFuncSetAttribute(k_gemm_hmma, cudaFuncAttributeMaxDynamicSharedMemorySize, GM_SMEM);

    k_convert_wt<<<dim3(8, 8, 64), dim3(32, 8)>>>(we);
    k_front     <<<NBF, 256>>>(x, wg);
    k_hist      <<<NCHUNK, 256>>>();
    k_scan      <<<E_NUM, 128>>>();
    k_rank      <<<NCHUNK, 1024>>>();
    k_gemm_hmma <<<dim3(CAPACITY / 128, 2, E_NUM), 256, GM_SMEM>>>();
    k_combine   <<<N_TOK / 4, 256>>>(out);
    k_loadsum   <<<E_NUM, 256>>>();
    k_aux       <<<1, 64>>>(out, out_size);
}

// round 6
// speedup vs baseline: 2.7693x; 1.4539x over previous
#include <cuda_runtime.h>
#include <cuda_fp16.h>
#include <cuda_bf16.h>
#include <math.h>
#include <stdint.h>

#define N_TOK    65536
#define C_DIM    256
#define E_NUM    64
#define S_SLOTS  131072
#define CAPACITY 2560
#define NCHUNK   128      /* S_SLOTS / 1024 */
#define NBF      512      /* front-end blocks (128 tokens each) */

// ---------------- scratch (device globals; no allocations) ----------------
__device__ int   g_eid[S_SLOTS];
__device__ float g_sc[S_SLOTS];
__device__ int   g_pos[S_SLOTS];
__device__ int   g_hist[NCHUNK * E_NUM];
__device__ int   g_chunkbase[NCHUNK * E_NUM];
__device__ int   g_kept[E_NUM];
__device__ int   g_tok[E_NUM * CAPACITY];
__device__ float g_ybuf[(size_t)E_NUM * CAPACITY * C_DIM];
__device__ float g_gatesum[NBF * E_NUM];
__device__ float g_load[E_NUM];
// fp16 operands
__device__ __half g_xh[(size_t)N_TOK * C_DIM];
__device__ __half g_wth[(size_t)E_NUM * C_DIM * C_DIM];  // [e][n][k]

// ---------------- packed fp32x2 helpers -------------------------------------
__device__ __forceinline__ unsigned long long splat2(float x) {
    unsigned long long r;
    asm("mov.b64 %0, {%1, %1};" : "=l"(r) : "f"(x));
    return r;
}
__device__ __forceinline__ void fma2(unsigned long long& d, unsigned long long a,
                                     unsigned long long b) {
    asm("fma.rn.f32x2 %0, %1, %2, %0;" : "+l"(d) : "l"(a), "l"(b));
}
__device__ __forceinline__ float lo2(unsigned long long v) { return __uint_as_float((unsigned)v); }
__device__ __forceinline__ float hi2(unsigned long long v) { return __uint_as_float((unsigned)(v >> 32)); }

// ---------------- mma.sync / cp.async helpers (base sm_103-safe) ------------
__device__ __forceinline__ uint32_t smem_u32(const void* p) {
    uint32_t a;
    asm("{ .reg .u64 t; cvta.to.shared.u64 t, %1; cvt.u32.u64 %0, t; }"
        : "=r"(a) : "l"(p));
    return a;
}
__device__ __forceinline__ void ldsm_x4(uint32_t* r, uint32_t a) {
    asm volatile("ldmatrix.sync.aligned.m8n8.x4.shared.b16 {%0,%1,%2,%3}, [%4];"
                 : "=r"(r[0]), "=r"(r[1]), "=r"(r[2]), "=r"(r[3]) : "r"(a));
}
__device__ __forceinline__ void ldsm_x2(uint32_t* r, uint32_t a) {
    asm volatile("ldmatrix.sync.aligned.m8n8.x2.shared.b16 {%0,%1}, [%2];"
                 : "=r"(r[0]), "=r"(r[1]) : "r"(a));
}
__device__ __forceinline__ void mma_f16(float* d, const uint32_t* a, const uint32_t* b) {
    asm volatile(
        "mma.sync.aligned.m16n8k16.row.col.f32.f16.f16.f32 "
        "{%0,%1,%2,%3}, {%4,%5,%6,%7}, {%8,%9}, {%0,%1,%2,%3};"
        : "+f"(d[0]), "+f"(d[1]), "+f"(d[2]), "+f"(d[3])
        : "r"(a[0]), "r"(a[1]), "r"(a[2]), "r"(a[3]), "r"(b[0]), "r"(b[1]));
}
__device__ __forceinline__ void cpa16(uint32_t dst, const void* src, int bytes) {
    asm volatile("cp.async.cg.shared.global [%0], [%1], 16, %2;"
                 :: "r"(dst), "l"(src), "r"(bytes));
}
#define CP_COMMIT() asm volatile("cp.async.commit_group;" ::: "memory")
#define CP_WAIT(n)  asm volatile("cp.async.wait_group %0;" :: "n"(n) : "memory")

// ---------------- K_front: convert x + logits + softmax/top2 (fused) --------
__global__ __launch_bounds__(256, 2) void k_front(const float* __restrict__ x,
                                                  const float* __restrict__ wg) {
    __shared__ char smbuf[34816];            // overlay: tiles then logits
    __shared__ float gs[8][64];
    float (*As)[132] = (float(*)[132])smbuf;           // 16x132 = 8448 B
    float (*Bs)[68]  = (float(*)[68])(smbuf + 8448);   // 16x68  = 4352 B
    float (*lgt)[68] = (float(*)[68])smbuf;            // 128x68 = 34816 B

    int tid = threadIdx.x, lane = tid & 31, w = tid >> 5;
    int tx = tid & 15, ty = tid >> 4;
    int row0 = blockIdx.x * 128;

    unsigned long long acc[8][2];
#pragma unroll
    for (int i = 0; i < 8; i++) { acc[i][0] = 0ULL; acc[i][1] = 0ULL; }

    const float4* x4 = (const float4*)x;
    const float4* w4 = (const float4*)wg;

    for (int kb = 0; kb < 16; kb++) {
        for (int l = tid; l < 512; l += 256) {
            int m = l >> 2, cs = l & 3;
            size_t gi = (size_t)(row0 + m) * 64 + kb * 4 + cs;
            float4 v = x4[gi];
            As[cs * 4 + 0][m] = v.x; As[cs * 4 + 1][m] = v.y;
            As[cs * 4 + 2][m] = v.z; As[cs * 4 + 3][m] = v.w;
            // inline fp16 conversion store
            __half2 p01 = __floats2half2_rn(v.x, v.y);
            __half2 p23 = __floats2half2_rn(v.z, v.w);
            uint2 ph;
            ph.x = *(unsigned*)&p01;
            ph.y = *(unsigned*)&p23;
            ((uint2*)g_xh)[gi] = ph;
        }
        {
            int kk = tid >> 4, n4 = tid & 15;
            float4 v = w4[(size_t)(kb * 16 + kk) * 16 + n4];
            *(float4*)&Bs[kk][n4 * 4] = v;
        }
        __syncthreads();
#pragma unroll
        for (int kk = 0; kk < 16; kk++) {
            ulonglong2 bb = *(const ulonglong2*)&Bs[kk][tx * 4];
            float a[8];
            *(float4*)&a[0] = *(const float4*)&As[kk][ty * 8];
            *(float4*)&a[4] = *(const float4*)&As[kk][ty * 8 + 4];
#pragma unroll
            for (int i = 0; i < 8; i++) {
                unsigned long long s = splat2(a[i]);
                fma2(acc[i][0], s, bb.x);
                fma2(acc[i][1], s, bb.y);
            }
        }
        __syncthreads();
    }

    // stash logits into SMEM (overlay on dead tiles)
#pragma unroll
    for (int i = 0; i < 8; i++) {
        float4 o;
        o.x = lo2(acc[i][0]); o.y = hi2(acc[i][0]);
        o.z = lo2(acc[i][1]); o.w = hi2(acc[i][1]);
        *(float4*)&lgt[ty * 8 + i][tx * 4] = o;
    }
    __syncthreads();

    // router: each warp handles 16 tokens
    float gsum_lo = 0.0f, gsum_hi = 0.0f;
    const float NEG = __int_as_float(0xff800000);
#pragma unroll 1
    for (int it = 0; it < 16; it++) {
        int t = w * 16 + it;
        float v0 = lgt[t][lane], v1 = lgt[t][lane + 32];

        float mx = fmaxf(v0, v1);
#pragma unroll
        for (int o = 16; o; o >>= 1) mx = fmaxf(mx, __shfl_xor_sync(0xffffffffu, mx, o));
        float e0 = expf(v0 - mx), e1 = expf(v1 - mx);
        float sum = e0 + e1;
#pragma unroll
        for (int o = 16; o; o >>= 1) sum += __shfl_xor_sync(0xffffffffu, sum, o);
        float g0 = e0 / sum, g1 = e1 / sum;
        gsum_lo += g0; gsum_hi += g1;

        float bv; int bi;
        if (v1 > v0) { bv = v1; bi = lane + 32; } else { bv = v0; bi = lane; }
#pragma unroll
        for (int o = 16; o; o >>= 1) {
            float ov = __shfl_xor_sync(0xffffffffu, bv, o);
            int   oi = __shfl_xor_sync(0xffffffffu, bi, o);
            if (ov > bv || (ov == bv && oi < bi)) { bv = ov; bi = oi; }
        }
        int i1 = bi;

        float w0 = (lane == i1) ? NEG : v0;
        float w1 = (lane + 32 == i1) ? NEG : v1;
        float cv; int ci;
        if (w1 > w0) { cv = w1; ci = lane + 32; } else { cv = w0; ci = lane; }
#pragma unroll
        for (int o = 16; o; o >>= 1) {
            float ov = __shfl_xor_sync(0xffffffffu, cv, o);
            int   oi = __shfl_xor_sync(0xffffffffu, ci, o);
            if (ov > cv || (ov == cv && oi < ci)) { cv = ov; ci = oi; }
        }
        int i2 = ci;

        float s1 = __shfl_sync(0xffffffffu, (i1 < 32) ? g0 : g1, i1 & 31);
        float s2 = __shfl_sync(0xffffffffu, (i2 < 32) ? g0 : g1, i2 & 31);

        if (lane == 0) {
            int tok = row0 + t;
            g_eid[2 * tok] = i1;     g_sc[2 * tok] = s1;
            g_eid[2 * tok + 1] = i2; g_sc[2 * tok + 1] = s2;
        }
    }
    gs[w][lane] = gsum_lo;
    gs[w][lane + 32] = gsum_hi;
    __syncthreads();
    if (tid < 64) {
        float s = 0.0f;
#pragma unroll
        for (int j = 0; j < 8; j++) s += gs[j][tid];
        g_gatesum[(size_t)blockIdx.x * 64 + tid] = s;
    }
}

// ---------------- K3: per-chunk expert histograms ---------------------------
__global__ __launch_bounds__(256) void k_hist() {
    __shared__ int h[64];
    int tid = threadIdx.x;
    if (tid < 64) h[tid] = 0;
    __syncthreads();
    int base = blockIdx.x * 1024;
#pragma unroll
    for (int j = 0; j < 4; j++) atomicAdd(&h[g_eid[base + j * 256 + tid]], 1);
    __syncthreads();
    if (tid < 64) g_hist[blockIdx.x * 64 + tid] = h[tid];
}

// ---------------- K4: parallel exclusive scan per expert --------------------
__global__ __launch_bounds__(128) void k_scan() {
    __shared__ int s[128];
    int e = blockIdx.x, t = threadIdx.x;
    int v = g_hist[t * 64 + e];
    s[t] = v;
    __syncthreads();
#pragma unroll
    for (int o = 1; o < 128; o <<= 1) {
        int x = (t >= o) ? s[t - o] : 0;
        __syncthreads();
        s[t] += x;
        __syncthreads();
    }
    g_chunkbase[t * 64 + e] = s[t] - v;
    if (t == 127) g_kept[e] = (s[127] < CAPACITY) ? s[127] : CAPACITY;
}

// ---------------- K5: FIFO ranks via warp ballots ---------------------------
__global__ __launch_bounds__(1024) void k_rank() {
    __shared__ int whist[32][64];
    int t = threadIdx.x, lane = t & 31, w = t >> 5;
    int slot = blockIdx.x * 1024 + t;
    int e = g_eid[slot];
    ((int*)whist)[t] = 0;
    ((int*)whist)[t + 1024] = 0;
    __syncthreads();
    unsigned peers = __match_any_sync(0xffffffffu, e);
    int lr = __popc(peers & ((1u << lane) - 1u));
    if (lr == 0) whist[w][e] = __popc(peers);
    __syncthreads();
    int base = g_chunkbase[blockIdx.x * 64 + e];
    for (int j = 0; j < w; j++) base += whist[j][e];
    int rank = base + lr;
    if (rank < CAPACITY) {
        int p = e * CAPACITY + rank;
        g_pos[slot] = p;
        g_tok[p] = slot >> 1;
    } else {
        g_pos[slot] = -1;
    }
}

// ---------------- K_cvw: W_e[k][n] -> Wt[e][n][k] fp16 ----------------------
__global__ void k_convert_wt(const float* __restrict__ we) {
    __shared__ float ts[32][33];
    int e = blockIdx.z, kt = blockIdx.y, nt = blockIdx.x;
    int tx = threadIdx.x, ty = threadIdx.y;  // (32,8)
    const float* src = we + ((size_t)e * 256 + (size_t)kt * 32) * 256 + nt * 32;
#pragma unroll
    for (int j = 0; j < 32; j += 8) ts[ty + j][tx] = src[(size_t)(ty + j) * 256 + tx];
    __syncthreads();
#pragma unroll
    for (int j = 0; j < 32; j += 8) {
        float vv = ts[tx][ty + j];
        size_t d = ((size_t)e * 256 + (size_t)nt * 32 + ty + j) * 256 + kt * 32 + tx;
        g_wth[d] = __float2half_rn(vv);
    }
}

// ---------------- K6: grouped GEMM, single-term fp16 HMMA, cp.async 2-stage -
// CTA: 128 gathered rows x 128 cols, K=256 in 4 chunks of 64.
// 8 warps, warp tile 64x32 (4 mt x 4 nt of m16n8k16). 2 CTAs/SM.
#define TB       (128 * 144)              /* 18432 B per tile */
#define ST_A     0
#define ST_B     (TB)
#define STAGE    (2 * TB)                 /* 36864 B */
#define OFF_TOK  (2 * STAGE)
#define GM_SMEM  (2 * STAGE + 512)        /* 74240 B */

__global__ __launch_bounds__(256, 2) void k_gemm_hmma() {
    extern __shared__ char sm[];
    const uint32_t smb = smem_u32(sm);
    int tid = threadIdx.x, lane = tid & 31, wid = tid >> 5;

    int e = blockIdx.z;
    int kept = g_kept[e];
    int m0 = blockIdx.x * 128;
    if (m0 >= kept) return;
    int n0 = blockIdx.y * 128;

    int* stok = (int*)(sm + OFF_TOK);
    if (tid < 128) {
        int r = m0 + tid;
        stok[tid] = (r < kept) ? g_tok[e * CAPACITY + r] : -1;
    }
    __syncthreads();

    const uint4* xh4 = (const uint4*)g_xh;
    const uint4* wh4 = (const uint4*)g_wth;

    // per-thread load coords: 4 (row,c8) pairs over 128x8 uint4
    int lrow[4], lc8[4];
    const uint4* asrc[4];
    const uint4* bsrc[4];
    int abytes[4];
#pragma unroll
    for (int j = 0; j < 4; j++) {
        int idx = j * 256 + tid;
        lrow[j] = idx >> 3;
        lc8[j] = idx & 7;
        int tk = stok[lrow[j]];
        int ok = tk >= 0;
        int tkc = ok ? tk : 0;
        asrc[j] = xh4 + (size_t)tkc * 32 + lc8[j];
        abytes[j] = ok ? 16 : 0;
        bsrc[j] = wh4 + (size_t)(e * 256 + n0 + lrow[j]) * 32 + lc8[j];
    }

    auto load_stage = [&](int kc, int s) {
        uint32_t sb = smb + s * STAGE;
        int koff = kc * 8;
#pragma unroll
        for (int j = 0; j < 4; j++) {
            uint32_t o = (uint32_t)(lrow[j] * 144 + lc8[j] * 16);
            cpa16(sb + ST_A + o, asrc[j] + koff, abytes[j]);
            cpa16(sb + ST_B + o, bsrc[j] + koff, 16);
        }
    };

    int wm = wid >> 2, wn = wid & 3;

    float acc[4][4][4];
#pragma unroll
    for (int mt = 0; mt < 4; mt++)
#pragma unroll
        for (int nt = 0; nt < 4; nt++)
#pragma unroll
            for (int q = 0; q < 4; q++) acc[mt][nt][q] = 0.0f;

    int a_m = lane >> 3, a_r = lane & 7;
    int b_l = lane & 15;

    load_stage(0, 0);
    CP_COMMIT();

#pragma unroll
    for (int kc = 0; kc < 4; kc++) {
        if (kc < 3) {
            load_stage(kc + 1, (kc + 1) & 1);
            CP_COMMIT();
            CP_WAIT(1);
        } else {
            CP_WAIT(0);
        }
        __syncthreads();

        uint32_t base = smb + (kc & 1) * STAGE;
#pragma unroll
        for (int ks = 0; ks < 4; ks++) {
            int k0 = ks * 16;
            uint32_t ah[4][4], bh[4][2];
#pragma unroll
            for (int mt = 0; mt < 4; mt++) {
                int arow = wm * 64 + mt * 16 + (a_m & 1) * 8 + a_r;
                int acol = k0 + (a_m >> 1) * 8;
                uint32_t off = (uint32_t)(arow * 144 + acol * 2);
                ldsm_x4(ah[mt], base + ST_A + off);
            }
#pragma unroll
            for (int nt = 0; nt < 4; nt++) {
                int brow = wn * 32 + nt * 8 + (b_l & 7);
                int bcol = k0 + ((b_l >> 3) & 1) * 8;
                uint32_t off = (uint32_t)(brow * 144 + bcol * 2);
                ldsm_x2(bh[nt], base + ST_B + off);
            }
#pragma unroll
            for (int mt = 0; mt < 4; mt++)
#pragma unroll
                for (int nt = 0; nt < 4; nt++)
                    mma_f16(acc[mt][nt], ah[mt], bh[nt]);
        }
        __syncthreads();
    }

    // ---- epilogue: stage through SMEM for coalesced stores ----
    float* fb = (float*)sm;                      // [128][132] = 67584 B < GM_SMEM
    int g = lane >> 2, c = lane & 3;
#pragma unroll
    for (int mt = 0; mt < 4; mt++) {
#pragma unroll
        for (int nt = 0; nt < 4; nt++) {
            int row = wm * 64 + mt * 16 + g;
            int col = wn * 32 + nt * 8 + c * 2;
            float2 v0 = make_float2(acc[mt][nt][0], acc[mt][nt][1]);
            float2 v1 = make_float2(acc[mt][nt][2], acc[mt][nt][3]);
            *(float2*)&fb[row * 132 + col] = v0;
            *(float2*)&fb[(row + 8) * 132 + col] = v1;
        }
    }
    __syncthreads();
    int c4 = tid & 31;
#pragma unroll
    for (int rp = 0; rp < 16; rp++) {
        int row = rp * 8 + (tid >> 5);
        if (m0 + row < kept) {
            float4 v = *(const float4*)&fb[row * 132 + c4 * 4];
            *(float4*)(g_ybuf + ((size_t)e * CAPACITY + m0 + row) * 256 + n0 + c4 * 4) = v;
        }
    }
}

// ---------------- K_combine --------------------------------------------------
__global__ __launch_bounds__(256) void k_combine(float* __restrict__ out) {
    int idx = blockIdx.x * 256 + threadIdx.x;
    int tok = idx >> 6, c4 = idx & 63;
    int p0 = g_pos[2 * tok], p1 = g_pos[2 * tok + 1];
    float s0 = g_sc[2 * tok], s1 = g_sc[2 * tok + 1];
    float4 r = make_float4(0.f, 0.f, 0.f, 0.f);
    const float4* yb = (const float4*)g_ybuf;
    if (p0 >= 0) {
        float4 y = yb[(size_t)p0 * 64 + c4];
        r.x = s0 * y.x; r.y = s0 * y.y; r.z = s0 * y.z; r.w = s0 * y.w;
    }
    if (p1 >= 0) {
        float4 y = yb[(size_t)p1 * 64 + c4];
        r.x += s1 * y.x; r.y += s1 * y.y; r.z += s1 * y.z; r.w += s1 * y.w;
    }
    ((float4*)out)[idx] = r;
}

// ---------------- aux loss ---------------------------------------------------
__global__ __launch_bounds__(256) void k_loadsum() {
    __shared__ float sh[256];
    int e = blockIdx.x;
    float s = 0.0f;
    for (int b = threadIdx.x; b < NBF; b += 256) s += g_gatesum[(size_t)b * 64 + e];
    sh[threadIdx.x] = s;
    __syncthreads();
    for (int o = 128; o; o >>= 1) {
        if (threadIdx.x < o) sh[threadIdx.x] += sh[threadIdx.x + o];
        __syncthreads();
    }
    if (threadIdx.x == 0) g_load[e] = sh[0];
}

__global__ void k_aux(float* __restrict__ out, int out_size) {
    __shared__ float sh[64];
    int e = threadIdx.x;
    float load = g_load[e] / (float)N_TOK;
    float d = load - (1.0f / 64.0f);
    sh[e] = d * d;
    __syncthreads();
    for (int o = 32; o; o >>= 1) {
        if (e < o) sh[e] += sh[e + o];
        __syncthreads();
    }
    if (e == 0 && out_size > N_TOK * C_DIM) out[N_TOK * C_DIM] = sh[0] / 64.0f;
}

// ---------------- launch ----------------------------------------------------
extern "C" void kernel_launch(void* const* d_in, const int* in_sizes, int n_in,
                              void* d_out, int out_size) {
    const float* x  = (const float*)d_in[0];
    const float* wg = (const float*)d_in[1];
    const float* we = (const float*)d_in[2];
    float* out = (float*)d_out;

    cudaFuncSetAttribute(k_gemm_hmma, cudaFuncAttributeMaxDynamicSharedMemorySize, GM_SMEM);

    k_convert_wt<<<dim3(8, 8, 64), dim3(32, 8)>>>(we);
    k_front     <<<NBF, 256>>>(x, wg);
    k_hist      <<<NCHUNK, 256>>>();
    k_scan      <<<E_NUM, 128>>>();
    k_rank      <<<NCHUNK, 1024>>>();
    k_gemm_hmma <<<dim3(CAPACITY / 128, 2, E_NUM), 256, GM_SMEM>>>();
    k_combine   <<<N_TOK / 4, 256>>>(out);
    k_loadsum   <<<E_NUM, 256>>>();
    k_aux       <<<1, 64>>>(out, out_size);
}

// round 7
// speedup vs baseline: 3.0528x; 1.1024x over previous
#include <cuda_runtime.h>
#include <cuda_fp16.h>
#include <math.h>
#include <stdint.h>

#define N_TOK    65536
#define C_DIM    256
#define E_NUM    64
#define S_SLOTS  131072
#define CAPACITY 2560
#define NCHUNK   128      /* S_SLOTS / 1024 */
#define NBF      512      /* front-end blocks (128 tokens each) */

// ---------------- scratch (device globals; no allocations) ----------------
__device__ int   g_eid[S_SLOTS];
__device__ float g_sc[S_SLOTS];
__device__ int   g_pos[S_SLOTS];
__device__ int   g_hist[NCHUNK * E_NUM];
__device__ int   g_chunkbase[NCHUNK * E_NUM];
__device__ int   g_kept[E_NUM];
__device__ int   g_tok[E_NUM * CAPACITY];
__device__ __half g_ybuf[(size_t)E_NUM * CAPACITY * C_DIM];   // fp16 now (84MB)
__device__ float g_gatesum[NBF * E_NUM];
__device__ float g_load[E_NUM];
// fp16 operands
__device__ __half g_xh[(size_t)N_TOK * C_DIM];
__device__ __half g_wth[(size_t)E_NUM * C_DIM * C_DIM];  // [e][n][k]

// ---------------- packed fp32x2 helpers -------------------------------------
__device__ __forceinline__ unsigned long long splat2(float x) {
    unsigned long long r;
    asm("mov.b64 %0, {%1, %1};" : "=l"(r) : "f"(x));
    return r;
}
__device__ __forceinline__ void fma2(unsigned long long& d, unsigned long long a,
                                     unsigned long long b) {
    asm("fma.rn.f32x2 %0, %1, %2, %0;" : "+l"(d) : "l"(a), "l"(b));
}
__device__ __forceinline__ float lo2(unsigned long long v) { return __uint_as_float((unsigned)v); }
__device__ __forceinline__ float hi2(unsigned long long v) { return __uint_as_float((unsigned)(v >> 32)); }

// ---------------- mma.sync / cp.async helpers (base sm_103-safe) ------------
__device__ __forceinline__ uint32_t smem_u32(const void* p) {
    uint32_t a;
    asm("{ .reg .u64 t; cvta.to.shared.u64 t, %1; cvt.u32.u64 %0, t; }"
        : "=r"(a) : "l"(p));
    return a;
}
__device__ __forceinline__ void ldsm_x4(uint32_t* r, uint32_t a) {
    asm volatile("ldmatrix.sync.aligned.m8n8.x4.shared.b16 {%0,%1,%2,%3}, [%4];"
                 : "=r"(r[0]), "=r"(r[1]), "=r"(r[2]), "=r"(r[3]) : "r"(a));
}
__device__ __forceinline__ void mma_f16(float* d, const uint32_t* a, const uint32_t* b) {
    asm volatile(
        "mma.sync.aligned.m16n8k16.row.col.f32.f16.f16.f32 "
        "{%0,%1,%2,%3}, {%4,%5,%6,%7}, {%8,%9}, {%0,%1,%2,%3};"
        : "+f"(d[0]), "+f"(d[1]), "+f"(d[2]), "+f"(d[3])
        : "r"(a[0]), "r"(a[1]), "r"(a[2]), "r"(a[3]), "r"(b[0]), "r"(b[1]));
}
__device__ __forceinline__ void cpa16(uint32_t dst, const void* src, int bytes) {
    asm volatile("cp.async.cg.shared.global [%0], [%1], 16, %2;"
                 :: "r"(dst), "l"(src), "r"(bytes));
}
#define CP_COMMIT() asm volatile("cp.async.commit_group;" ::: "memory")
#define CP_WAIT(n)  asm volatile("cp.async.wait_group %0;" :: "n"(n) : "memory")

// ---------------- K_front: convert x + logits + softmax/top2 (fused) --------
__global__ __launch_bounds__(256, 2) void k_front(const float* __restrict__ x,
                                                  const float* __restrict__ wg) {
    __shared__ char smbuf[34816];            // overlay: tiles then logits
    __shared__ float gs[8][64];
    float (*As)[132] = (float(*)[132])smbuf;           // 16x132 = 8448 B
    float (*Bs)[68]  = (float(*)[68])(smbuf + 8448);   // 16x68  = 4352 B
    float (*lgt)[68] = (float(*)[68])smbuf;            // 128x68 = 34816 B

    int tid = threadIdx.x, lane = tid & 31, w = tid >> 5;
    int tx = tid & 15, ty = tid >> 4;
    int row0 = blockIdx.x * 128;

    unsigned long long acc[8][2];
#pragma unroll
    for (int i = 0; i < 8; i++) { acc[i][0] = 0ULL; acc[i][1] = 0ULL; }

    const float4* x4 = (const float4*)x;
    const float4* w4 = (const float4*)wg;

    for (int kb = 0; kb < 16; kb++) {
        for (int l = tid; l < 512; l += 256) {
            int m = l >> 2, cs = l & 3;
            size_t gi = (size_t)(row0 + m) * 64 + kb * 4 + cs;
            float4 v = x4[gi];
            As[cs * 4 + 0][m] = v.x; As[cs * 4 + 1][m] = v.y;
            As[cs * 4 + 2][m] = v.z; As[cs * 4 + 3][m] = v.w;
            __half2 p01 = __floats2half2_rn(v.x, v.y);
            __half2 p23 = __floats2half2_rn(v.z, v.w);
            uint2 ph;
            ph.x = *(unsigned*)&p01;
            ph.y = *(unsigned*)&p23;
            ((uint2*)g_xh)[gi] = ph;
        }
        {
            int kk = tid >> 4, n4 = tid & 15;
            float4 v = w4[(size_t)(kb * 16 + kk) * 16 + n4];
            *(float4*)&Bs[kk][n4 * 4] = v;
        }
        __syncthreads();
#pragma unroll
        for (int kk = 0; kk < 16; kk++) {
            ulonglong2 bb = *(const ulonglong2*)&Bs[kk][tx * 4];
            float a[8];
            *(float4*)&a[0] = *(const float4*)&As[kk][ty * 8];
            *(float4*)&a[4] = *(const float4*)&As[kk][ty * 8 + 4];
#pragma unroll
            for (int i = 0; i < 8; i++) {
                unsigned long long s = splat2(a[i]);
                fma2(acc[i][0], s, bb.x);
                fma2(acc[i][1], s, bb.y);
            }
        }
        __syncthreads();
    }

#pragma unroll
    for (int i = 0; i < 8; i++) {
        float4 o;
        o.x = lo2(acc[i][0]); o.y = hi2(acc[i][0]);
        o.z = lo2(acc[i][1]); o.w = hi2(acc[i][1]);
        *(float4*)&lgt[ty * 8 + i][tx * 4] = o;
    }
    __syncthreads();

    float gsum_lo = 0.0f, gsum_hi = 0.0f;
    const float NEG = __int_as_float(0xff800000);
#pragma unroll 1
    for (int it = 0; it < 16; it++) {
        int t = w * 16 + it;
        float v0 = lgt[t][lane], v1 = lgt[t][lane + 32];

        float mx = fmaxf(v0, v1);
#pragma unroll
        for (int o = 16; o; o >>= 1) mx = fmaxf(mx, __shfl_xor_sync(0xffffffffu, mx, o));
        float e0 = expf(v0 - mx), e1 = expf(v1 - mx);
        float sum = e0 + e1;
#pragma unroll
        for (int o = 16; o; o >>= 1) sum += __shfl_xor_sync(0xffffffffu, sum, o);
        float g0 = e0 / sum, g1 = e1 / sum;
        gsum_lo += g0; gsum_hi += g1;

        float bv; int bi;
        if (v1 > v0) { bv = v1; bi = lane + 32; } else { bv = v0; bi = lane; }
#pragma unroll
        for (int o = 16; o; o >>= 1) {
            float ov = __shfl_xor_sync(0xffffffffu, bv, o);
            int   oi = __shfl_xor_sync(0xffffffffu, bi, o);
            if (ov > bv || (ov == bv && oi < bi)) { bv = ov; bi = oi; }
        }
        int i1 = bi;

        float w0 = (lane == i1) ? NEG : v0;
        float w1 = (lane + 32 == i1) ? NEG : v1;
        float cv; int ci;
        if (w1 > w0) { cv = w1; ci = lane + 32; } else { cv = w0; ci = lane; }
#pragma unroll
        for (int o = 16; o; o >>= 1) {
            float ov = __shfl_xor_sync(0xffffffffu, cv, o);
            int   oi = __shfl_xor_sync(0xffffffffu, ci, o);
            if (ov > cv || (ov == cv && oi < ci)) { cv = ov; ci = oi; }
        }
        int i2 = ci;

        float s1 = __shfl_sync(0xffffffffu, (i1 < 32) ? g0 : g1, i1 & 31);
        float s2 = __shfl_sync(0xffffffffu, (i2 < 32) ? g0 : g1, i2 & 31);

        if (lane == 0) {
            int tok = row0 + t;
            g_eid[2 * tok] = i1;     g_sc[2 * tok] = s1;
            g_eid[2 * tok + 1] = i2; g_sc[2 * tok + 1] = s2;
        }
    }
    gs[w][lane] = gsum_lo;
    gs[w][lane + 32] = gsum_hi;
    __syncthreads();
    if (tid < 64) {
        float s = 0.0f;
#pragma unroll
        for (int j = 0; j < 8; j++) s += gs[j][tid];
        g_gatesum[(size_t)blockIdx.x * 64 + tid] = s;
    }
}

// ---------------- K3: per-chunk expert histograms ---------------------------
__global__ __launch_bounds__(256) void k_hist() {
    __shared__ int h[64];
    int tid = threadIdx.x;
    if (tid < 64) h[tid] = 0;
    __syncthreads();
    int base = blockIdx.x * 1024;
#pragma unroll
    for (int j = 0; j < 4; j++) atomicAdd(&h[g_eid[base + j * 256 + tid]], 1);
    __syncthreads();
    if (tid < 64) g_hist[blockIdx.x * 64 + tid] = h[tid];
}

// ---------------- K4: parallel exclusive scan per expert --------------------
__global__ __launch_bounds__(128) void k_scan() {
    __shared__ int s[128];
    int e = blockIdx.x, t = threadIdx.x;
    int v = g_hist[t * 64 + e];
    s[t] = v;
    __syncthreads();
#pragma unroll
    for (int o = 1; o < 128; o <<= 1) {
        int x = (t >= o) ? s[t - o] : 0;
        __syncthreads();
        s[t] += x;
        __syncthreads();
    }
    g_chunkbase[t * 64 + e] = s[t] - v;
    if (t == 127) g_kept[e] = (s[127] < CAPACITY) ? s[127] : CAPACITY;
}

// ---------------- K5: FIFO ranks via warp ballots ---------------------------
__global__ __launch_bounds__(1024) void k_rank() {
    __shared__ int whist[32][64];
    int t = threadIdx.x, lane = t & 31, w = t >> 5;
    int slot = blockIdx.x * 1024 + t;
    int e = g_eid[slot];
    ((int*)whist)[t] = 0;
    ((int*)whist)[t + 1024] = 0;
    __syncthreads();
    unsigned peers = __match_any_sync(0xffffffffu, e);
    int lr = __popc(peers & ((1u << lane) - 1u));
    if (lr == 0) whist[w][e] = __popc(peers);
    __syncthreads();
    int base = g_chunkbase[blockIdx.x * 64 + e];
    for (int j = 0; j < w; j++) base += whist[j][e];
    int rank = base + lr;
    if (rank < CAPACITY) {
        int p = e * CAPACITY + rank;
        g_pos[slot] = p;
        g_tok[p] = slot >> 1;
    } else {
        g_pos[slot] = -1;
    }
}

// ---------------- K_cvw: W_e[k][n] -> Wt[e][n][k] fp16 ----------------------
__global__ void k_convert_wt(const float* __restrict__ we) {
    __shared__ float ts[32][33];
    int e = blockIdx.z, kt = blockIdx.y, nt = blockIdx.x;
    int tx = threadIdx.x, ty = threadIdx.y;  // (32,8)
    const float* src = we + ((size_t)e * 256 + (size_t)kt * 32) * 256 + nt * 32;
#pragma unroll
    for (int j = 0; j < 32; j += 8) ts[ty + j][tx] = src[(size_t)(ty + j) * 256 + tx];
    __syncthreads();
#pragma unroll
    for (int j = 0; j < 32; j += 8) {
        float vv = ts[tx][ty + j];
        size_t d = ((size_t)e * 256 + (size_t)nt * 32 + ty + j) * 256 + kt * 32 + tx;
        g_wth[d] = __float2half_rn(vv);
    }
}

// ---------------- K6: grouped GEMM, fp16 HMMA, cp.async 2-stage -------------
#define TB       (128 * 144)              /* 18432 B per tile */
#define ST_A     0
#define ST_B     (TB)
#define STAGE    (2 * TB)                 /* 36864 B */
#define OFF_TOK  (2 * STAGE)
#define GM_SMEM  (2 * STAGE + 512)        /* 74240 B */

__global__ __launch_bounds__(256, 2) void k_gemm_hmma() {
    extern __shared__ char sm[];
    const uint32_t smb = smem_u32(sm);
    int tid = threadIdx.x, lane = tid & 31, wid = tid >> 5;

    int e = blockIdx.z;
    int kept = g_kept[e];
    int m0 = blockIdx.x * 128;
    if (m0 >= kept) return;
    int n0 = blockIdx.y * 128;

    int* stok = (int*)(sm + OFF_TOK);
    if (tid < 128) {
        int r = m0 + tid;
        stok[tid] = (r < kept) ? g_tok[e * CAPACITY + r] : -1;
    }
    __syncthreads();

    const uint4* xh4 = (const uint4*)g_xh;
    const uint4* wh4 = (const uint4*)g_wth;

    int lrow[4], lc8[4];
    const uint4* asrc[4];
    const uint4* bsrc[4];
    int abytes[4];
#pragma unroll
    for (int j = 0; j < 4; j++) {
        int idx = j * 256 + tid;
        lrow[j] = idx >> 3;
        lc8[j] = idx & 7;
        int tk = stok[lrow[j]];
        int ok = tk >= 0;
        int tkc = ok ? tk : 0;
        asrc[j] = xh4 + (size_t)tkc * 32 + lc8[j];
        abytes[j] = ok ? 16 : 0;
        bsrc[j] = wh4 + (size_t)(e * 256 + n0 + lrow[j]) * 32 + lc8[j];
    }

    auto load_stage = [&](int kc, int s) {
        uint32_t sb = smb + s * STAGE;
        int koff = kc * 8;
#pragma unroll
        for (int j = 0; j < 4; j++) {
            uint32_t o = (uint32_t)(lrow[j] * 144 + lc8[j] * 16);
            cpa16(sb + ST_A + o, asrc[j] + koff, abytes[j]);
            cpa16(sb + ST_B + o, bsrc[j] + koff, 16);
        }
    };

    int wm = wid >> 2, wn = wid & 3;

    float acc[4][4][4];
#pragma unroll
    for (int mt = 0; mt < 4; mt++)
#pragma unroll
        for (int nt = 0; nt < 4; nt++)
#pragma unroll
            for (int q = 0; q < 4; q++) acc[mt][nt][q] = 0.0f;

    int a_m = lane >> 3, a_r = lane & 7;

    load_stage(0, 0);
    CP_COMMIT();

#pragma unroll
    for (int kc = 0; kc < 4; kc++) {
        if (kc < 3) {
            load_stage(kc + 1, (kc + 1) & 1);
            CP_COMMIT();
            CP_WAIT(1);
        } else {
            CP_WAIT(0);
        }
        __syncthreads();

        uint32_t base = smb + (kc & 1) * STAGE;
#pragma unroll
        for (int ks = 0; ks < 4; ks++) {
            int k0 = ks * 16;
            uint32_t ah[4][4], bh[4][2];
#pragma unroll
            for (int mt = 0; mt < 4; mt++) {
                int arow = wm * 64 + mt * 16 + (a_m & 1) * 8 + a_r;
                int acol = k0 + (a_m >> 1) * 8;
                uint32_t off = (uint32_t)(arow * 144 + acol * 2);
                ldsm_x4(ah[mt], base + ST_A + off);
            }
            // B via x4: each inst loads fragments for 2 adjacent n-tiles
#pragma unroll
            for (int np = 0; np < 2; np++) {
                int brow = wn * 32 + (np * 2 + (lane >> 4)) * 8 + (lane & 7);
                int bcol = k0 + ((lane >> 3) & 1) * 8;
                uint32_t off = (uint32_t)(brow * 144 + bcol * 2);
                uint32_t r[4];
                ldsm_x4(r, base + ST_B + off);
                bh[np * 2][0] = r[0]; bh[np * 2][1] = r[1];
                bh[np * 2 + 1][0] = r[2]; bh[np * 2 + 1][1] = r[3];
            }
#pragma unroll
            for (int mt = 0; mt < 4; mt++)
#pragma unroll
                for (int nt = 0; nt < 4; nt++)
                    mma_f16(acc[mt][nt], ah[mt], bh[nt]);
        }
        __syncthreads();
    }

    // ---- epilogue: convert to fp16, stage through SMEM, coalesced stores ----
    __half* fb = (__half*)sm;                    // [128][136] halves = 34816 B
    int g = lane >> 2, c = lane & 3;
#pragma unroll
    for (int mt = 0; mt < 4; mt++) {
#pragma unroll
        for (int nt = 0; nt < 4; nt++) {
            int row = wm * 64 + mt * 16 + g;
            int col = wn * 32 + nt * 8 + c * 2;
            __half2 v0 = __floats2half2_rn(acc[mt][nt][0], acc[mt][nt][1]);
            __half2 v1 = __floats2half2_rn(acc[mt][nt][2], acc[mt][nt][3]);
            *(__half2*)&fb[row * 136 + col] = v0;
            *(__half2*)&fb[(row + 8) * 136 + col] = v1;
        }
    }
    __syncthreads();
#pragma unroll
    for (int it = 0; it < 8; it++) {
        int idx = it * 256 + tid;           // 2048 uint4 total
        int row = idx >> 4, c16 = idx & 15;
        if (m0 + row < kept) {
            uint4 v = *(const uint4*)&fb[row * 136 + c16 * 8];
            *(uint4*)(g_ybuf + ((size_t)e * CAPACITY + m0 + row) * 256 + n0 + c16 * 8) = v;
        }
    }
}

// ---------------- K_combine: fp16 ybuf, 8 outputs per thread ----------------
__global__ __launch_bounds__(256) void k_combine(float* __restrict__ out) {
    int idx = blockIdx.x * 256 + threadIdx.x;   // over N_TOK*32
    int tok = idx >> 5, c8 = idx & 31;          // 8 halves per thread
    int p0 = g_pos[2 * tok], p1 = g_pos[2 * tok + 1];
    float s0 = g_sc[2 * tok], s1 = g_sc[2 * tok + 1];
    float r[8];
#pragma unroll
    for (int j = 0; j < 8; j++) r[j] = 0.0f;
    const uint4* yb = (const uint4*)g_ybuf;
    if (p0 >= 0) {
        uint4 v = yb[(size_t)p0 * 32 + c8];
        unsigned u[4] = {v.x, v.y, v.z, v.w};
#pragma unroll
        for (int j = 0; j < 4; j++) {
            float2 f = __half22float2(*(__half2*)&u[j]);
            r[2 * j] = s0 * f.x; r[2 * j + 1] = s0 * f.y;
        }
    }
    if (p1 >= 0) {
        uint4 v = yb[(size_t)p1 * 32 + c8];
        unsigned u[4] = {v.x, v.y, v.z, v.w};
#pragma unroll
        for (int j = 0; j < 4; j++) {
            float2 f = __half22float2(*(__half2*)&u[j]);
            r[2 * j] += s1 * f.x; r[2 * j + 1] += s1 * f.y;
        }
    }
    float4* o = (float4*)(out + (size_t)tok * 256 + c8 * 8);
    o[0] = make_float4(r[0], r[1], r[2], r[3]);
    o[1] = make_float4(r[4], r[5], r[6], r[7]);
}

// ---------------- aux loss ---------------------------------------------------
__global__ __launch_bounds__(256) void k_loadsum() {
    __shared__ float sh[256];
    int e = blockIdx.x;
    float s = 0.0f;
    for (int b = threadIdx.x; b < NBF; b += 256) s += g_gatesum[(size_t)b * 64 + e];
    sh[threadIdx.x] = s;
    __syncthreads();
    for (int o = 128; o; o >>= 1) {
        if (threadIdx.x < o) sh[threadIdx.x] += sh[threadIdx.x + o];
        __syncthreads();
    }
    if (threadIdx.x == 0) g_load[e] = sh[0];
}

__global__ void k_aux(float* __restrict__ out, int out_size) {
    __shared__ float sh[64];
    int e = threadIdx.x;
    float load = g_load[e] / (float)N_TOK;
    float d = load - (1.0f / 64.0f);
    sh[e] = d * d;
    __syncthreads();
    for (int o = 32; o; o >>= 1) {
        if (e < o) sh[e] += sh[e + o];
        __syncthreads();
    }
    if (e == 0 && out_size > N_TOK * C_DIM) out[N_TOK * C_DIM] = sh[0] / 64.0f;
}

// ---------------- launch ----------------------------------------------------
extern "C" void kernel_launch(void* const* d_in, const int* in_sizes, int n_in,
                              void* d_out, int out_size) {
    const float* x  = (const float*)d_in[0];
    const float* wg = (const float*)d_in[1];
    const float* we = (const float*)d_in[2];
    float* out = (float*)d_out;

    cudaFuncSetAttribute(k_gemm_hmma, cudaFuncAttributeMaxDynamicSharedMemorySize, GM_SMEM);

    k_convert_wt<<<dim3(8, 8, 64), dim3(32, 8)>>>(we);
    k_front     <<<NBF, 256>>>(x, wg);
    k_hist      <<<NCHUNK, 256>>>();
    k_scan      <<<E_NUM, 128>>>();
    k_rank      <<<NCHUNK, 1024>>>();
    k_gemm_hmma <<<dim3(CAPACITY / 128, 2, E_NUM), 256, GM_SMEM>>>();
    k_combine   <<<N_TOK / 8, 256>>>(out);
    k_loadsum   <<<E_NUM, 256>>>();
    k_aux       <<<1, 64>>>(out, out_size);
}